// round 5
// baseline (speedup 1.0000x reference)
#include <cuda_runtime.h>
#include <cuda_bf16.h>
#include <mma.h>
#include <cstdint>
#include <math.h>

using namespace nvcuda;

// ----------------------------------------------------------------------------
// Problem constants
// ----------------------------------------------------------------------------
#define Bn   4
#define Sn   2048
#define Dn   1024
#define Hn   16
#define HDn  64
#define Mrows (Bn*Sn)          // 8192
#define D4   (4*Dn)            // 4096

// ----------------------------------------------------------------------------
// Scratch (device globals -- no allocations allowed)
// ----------------------------------------------------------------------------
__device__ float         g_qkv  [(size_t)Mrows * 3 * Dn];
__device__ __nv_bfloat16 g_hA_hi[(size_t)Mrows * Dn];
__device__ __nv_bfloat16 g_hA_lo[(size_t)Mrows * Dn];
__device__ __nv_bfloat16 g_at_hi[(size_t)Mrows * Dn];
__device__ __nv_bfloat16 g_at_lo[(size_t)Mrows * Dn];
__device__ __nv_bfloat16 g_h1_hi[(size_t)Mrows * D4];
__device__ __nv_bfloat16 g_h1_lo[(size_t)Mrows * D4];
__device__ __nv_bfloat16 g_wqkvT_hi[(size_t)3 * Dn * Dn];
__device__ __nv_bfloat16 g_wqkvT_lo[(size_t)3 * Dn * Dn];
__device__ __nv_bfloat16 g_woT_hi[(size_t)Dn * Dn];
__device__ __nv_bfloat16 g_woT_lo[(size_t)Dn * Dn];
__device__ __nv_bfloat16 g_w1T_hi[(size_t)D4 * Dn];
__device__ __nv_bfloat16 g_w1T_lo[(size_t)D4 * Dn];
__device__ __nv_bfloat16 g_w2T_hi[(size_t)Dn * D4];
__device__ __nv_bfloat16 g_w2T_lo[(size_t)Dn * D4];
__device__ float         g_bp[3 * Dn];

__device__ __forceinline__ void split_bf16(float v, __nv_bfloat16& h, __nv_bfloat16& l) {
    h = __float2bfloat16(v);
    l = __float2bfloat16(v - __bfloat162float(h));
}

__device__ __forceinline__ uint32_t smem_u32(const void* p) {
    uint32_t a;
    asm("{ .reg .u64 t; cvta.to.shared.u64 t, %1; cvt.u32.u64 %0, t; }" : "=r"(a) : "l"(p));
    return a;
}
__device__ __forceinline__ void cp_async16(void* dst, const void* src) {
    asm volatile("cp.async.cg.shared.global [%0], [%1], 16;"
                 :: "r"(smem_u32(dst)), "l"(src) : "memory");
}
#define CP_COMMIT() asm volatile("cp.async.commit_group;" ::: "memory")
#define CP_WAIT(n)  asm volatile("cp.async.wait_group %0;" :: "n"(n) : "memory")

// ----------------------------------------------------------------------------
// Transpose + bf16 split: src [Ks, Ns] fp32  ->  dst [Ns, Ks] hi/lo bf16 rows.
// ----------------------------------------------------------------------------
__global__ void transpose_pack_kernel(const float* __restrict__ src,
                                      __nv_bfloat16* __restrict__ dhi,
                                      __nv_bfloat16* __restrict__ dlo,
                                      int Ks, int Ns, long long src_zoff,
                                      int out_row_base, int out_stride)
{
    __shared__ float t[32][33];
    int z = blockIdx.z;
    src += (size_t)z * src_zoff;
    int n0 = blockIdx.x * 32, k0 = blockIdx.y * 32;
    int tx = threadIdx.x, ty = threadIdx.y;
    #pragma unroll
    for (int j = 0; j < 4; j++) {
        int k = k0 + ty + j * 8;
        t[ty + j * 8][tx] = src[(size_t)k * Ns + n0 + tx];
    }
    __syncthreads();
    #pragma unroll
    for (int j = 0; j < 4; j++) {
        int n = n0 + ty + j * 8;
        float v = t[tx][ty + j * 8];
        __nv_bfloat16 h, l; split_bf16(v, h, l);
        size_t o = (size_t)(out_row_base + z * Ns + n) * out_stride + k0 + tx;
        dhi[o] = h; dlo[o] = l;
    }
}

__global__ void bias_pack_kernel(const float* __restrict__ bq,
                                 const float* __restrict__ bk,
                                 const float* __restrict__ bv,
                                 float* __restrict__ bp)
{
    int idx = blockIdx.x * 256 + threadIdx.x;
    if (idx < 3 * Dn) {
        int w = idx >> 10, c = idx & 1023;
        bp[idx] = (w == 0 ? bq : w == 1 ? bk : bv)[c];
    }
}

// ----------------------------------------------------------------------------
// LayerNorm -> bf16 hi/lo. One block per row, 256 threads, 4 elems each.
// ----------------------------------------------------------------------------
__global__ void __launch_bounds__(256) ln_kernel(const float* __restrict__ X,
                                                 const float* __restrict__ gamma,
                                                 const float* __restrict__ beta,
                                                 __nv_bfloat16* __restrict__ Yhi,
                                                 __nv_bfloat16* __restrict__ Ylo)
{
    int row = blockIdx.x;
    int tid = threadIdx.x;
    float4 xv = ((const float4*)(X + (size_t)row * Dn))[tid];

    __shared__ float red[8];
    float s = xv.x + xv.y + xv.z + xv.w;
    #pragma unroll
    for (int o = 16; o > 0; o >>= 1) s += __shfl_xor_sync(0xffffffffu, s, o);
    if ((tid & 31) == 0) red[tid >> 5] = s;
    __syncthreads();
    float mu = (red[0]+red[1]+red[2]+red[3]+red[4]+red[5]+red[6]+red[7]) * (1.0f / Dn);
    __syncthreads();

    float dx = xv.x - mu, dy = xv.y - mu, dz = xv.z - mu, dw = xv.w - mu;
    float sq = dx*dx + dy*dy + dz*dz + dw*dw;
    #pragma unroll
    for (int o = 16; o > 0; o >>= 1) sq += __shfl_xor_sync(0xffffffffu, sq, o);
    if ((tid & 31) == 0) red[tid >> 5] = sq;
    __syncthreads();
    float var = (red[0]+red[1]+red[2]+red[3]+red[4]+red[5]+red[6]+red[7]) * (1.0f / Dn);
    float inv = rsqrtf(var + 1e-5f);

    float4 gv = ((const float4*)gamma)[tid];
    float4 bv = ((const float4*)beta)[tid];
    float o0 = dx*inv*gv.x + bv.x, o1 = dy*inv*gv.y + bv.y;
    float o2 = dz*inv*gv.z + bv.z, o3 = dw*inv*gv.w + bv.w;

    __nv_bfloat16 h[4], l[4];
    split_bf16(o0, h[0], l[0]); split_bf16(o1, h[1], l[1]);
    split_bf16(o2, h[2], l[2]); split_bf16(o3, h[3], l[3]);
    size_t off = (size_t)row * Dn + tid * 4;
    *(__nv_bfloat162*)&Yhi[off]     = __nv_bfloat162(h[0], h[1]);
    *(__nv_bfloat162*)&Yhi[off + 2] = __nv_bfloat162(h[2], h[3]);
    *(__nv_bfloat162*)&Ylo[off]     = __nv_bfloat162(l[0], l[1]);
    *(__nv_bfloat162*)&Ylo[off + 2] = __nv_bfloat162(l[2], l[3]);
}

// ----------------------------------------------------------------------------
// WMMA bf16 GEMM, 2-stage cp.async, BK=32, 2 CTAs/SM (16 warps/SM).
// C[128x128 fp32] = A[128,K] . B^T, hi/lo 3-pass (Ah.Bh + Ah.Bl + Al.Bh),
// each pass sweeps all 8 accumulators -> 8 independent HMMA chains.
// ----------------------------------------------------------------------------
__device__ __forceinline__ float gelu_exact(float v) {
    return 0.5f * v * (1.0f + erff(v * 0.70710678118654752f));
}

#define BK     32
#define KPITCH 40                    // bf16/row (32 + 8 pad) = 80B pitch
#define TILEB  (128 * KPITCH * 2)    // 10240 B per matrix tile
#define STAGEB (4 * TILEB)           // 40960 B per stage (Ah, Al, Bh, Bl)
#define NSTAGE 2
#define GEMM_SMEM (NSTAGE * STAGEB)  // 81920 B  -> 2 CTAs/SM
#define SPITCH 132                   // fp32 staging pitch (67584 B, fits)

template <bool GELU_, bool RES_, bool OUTF, bool OUTB>
__global__ void __launch_bounds__(256, 2) mma_gemm_kernel(
    const __nv_bfloat16* __restrict__ Ahi, const __nv_bfloat16* __restrict__ Alo,
    const __nv_bfloat16* __restrict__ Bhi, const __nv_bfloat16* __restrict__ Blo,
    const float* __restrict__ bias, const float* __restrict__ residual,
    float* __restrict__ Cf, __nv_bfloat16* __restrict__ Chi, __nv_bfloat16* __restrict__ Clo,
    int N, int K)
{
    extern __shared__ __align__(128) char smem[];
    float* stg = (float*)smem;   // epilogue staging overlays tiles

    const int tid = threadIdx.x;
    const int wid = tid >> 5;
    const int wm = wid >> 2;          // 0..1  (64-row band)
    const int wn = wid & 3;           // 0..3  (32-col band)
    const int bx = blockIdx.x, by = blockIdx.y;

    const size_t arow = (size_t)by * 128;
    const size_t brow = (size_t)bx * 128;

    // Per chunk: 4 tiles of 128x32 bf16 = 512 float4 each; 2 f4/thread/tile.
    auto load_chunk = [&](int kc, int st) {
        char* base = smem + st * STAGEB;
        __nv_bfloat16* Ah_s = (__nv_bfloat16*)(base + 0 * TILEB);
        __nv_bfloat16* Al_s = (__nv_bfloat16*)(base + 1 * TILEB);
        __nv_bfloat16* Bh_s = (__nv_bfloat16*)(base + 2 * TILEB);
        __nv_bfloat16* Bl_s = (__nv_bfloat16*)(base + 3 * TILEB);
        #pragma unroll
        for (int i = 0; i < 2; i++) {
            int idx = tid + i * 256;
            int row = idx >> 2, c = idx & 3;         // 4 f4 per 32-col row
            size_t ao = (arow + row) * (size_t)K + kc * BK + c * 8;
            size_t bo = (brow + row) * (size_t)K + kc * BK + c * 8;
            int so = row * KPITCH + c * 8;
            cp_async16(&Ah_s[so], Ahi + ao);
            cp_async16(&Al_s[so], Alo + ao);
            cp_async16(&Bh_s[so], Bhi + bo);
            cp_async16(&Bl_s[so], Blo + bo);
        }
    };

    wmma::fragment<wmma::accumulator, 16, 16, 16, float> acc[4][2];
    #pragma unroll
    for (int i = 0; i < 4; i++)
        #pragma unroll
        for (int j = 0; j < 2; j++) wmma::fill_fragment(acc[i][j], 0.0f);

    const int nk = K / BK;

    load_chunk(0, 0); CP_COMMIT();

    for (int kc = 0; kc < nk; kc++) {
        const int st = kc & 1;
        if (kc + 1 < nk) { load_chunk(kc + 1, (kc + 1) & 1); CP_COMMIT(); }
        if (kc + 1 < nk) CP_WAIT(1); else CP_WAIT(0);
        __syncthreads();

        char* base = smem + st * STAGEB;
        __nv_bfloat16* Ah_s = (__nv_bfloat16*)(base + 0 * TILEB);
        __nv_bfloat16* Al_s = (__nv_bfloat16*)(base + 1 * TILEB);
        __nv_bfloat16* Bh_s = (__nv_bfloat16*)(base + 2 * TILEB);
        __nv_bfloat16* Bl_s = (__nv_bfloat16*)(base + 3 * TILEB);

        #pragma unroll
        for (int ks = 0; ks < BK / 16; ks++) {
            wmma::fragment<wmma::matrix_a, 16, 16, 16, __nv_bfloat16, wmma::row_major> a[4];
            wmma::fragment<wmma::matrix_b, 16, 16, 16, __nv_bfloat16, wmma::col_major> bh[2], bl[2];
            #pragma unroll
            for (int j = 0; j < 2; j++) {
                wmma::load_matrix_sync(bh[j], Bh_s + (wn * 32 + j * 16) * KPITCH + ks * 16, KPITCH);
                wmma::load_matrix_sync(bl[j], Bl_s + (wn * 32 + j * 16) * KPITCH + ks * 16, KPITCH);
            }
            #pragma unroll
            for (int i = 0; i < 4; i++)
                wmma::load_matrix_sync(a[i], Ah_s + (wm * 64 + i * 16) * KPITCH + ks * 16, KPITCH);
            // pass 1: Ah.Bh -- 8 independent acc chains
            #pragma unroll
            for (int i = 0; i < 4; i++)
                #pragma unroll
                for (int j = 0; j < 2; j++)
                    wmma::mma_sync(acc[i][j], a[i], bh[j], acc[i][j]);
            // pass 2: Ah.Bl
            #pragma unroll
            for (int i = 0; i < 4; i++)
                #pragma unroll
                for (int j = 0; j < 2; j++)
                    wmma::mma_sync(acc[i][j], a[i], bl[j], acc[i][j]);
            // pass 3: Al.Bh
            #pragma unroll
            for (int i = 0; i < 4; i++)
                wmma::load_matrix_sync(a[i], Al_s + (wm * 64 + i * 16) * KPITCH + ks * 16, KPITCH);
            #pragma unroll
            for (int i = 0; i < 4; i++)
                #pragma unroll
                for (int j = 0; j < 2; j++)
                    wmma::mma_sync(acc[i][j], a[i], bh[j], acc[i][j]);
        }
        __syncthreads();
    }

    // Stage accumulators to smem, then fused epilogue to GMEM.
    #pragma unroll
    for (int i = 0; i < 4; i++)
        #pragma unroll
        for (int j = 0; j < 2; j++) {
            int r0 = wm * 64 + i * 16, c0 = wn * 32 + j * 16;
            wmma::store_matrix_sync(&stg[r0 * SPITCH + c0], acc[i][j], SPITCH, wmma::mem_row_major);
        }
    __syncthreads();

    const int cc = tid & 31;
    const int ncol = bx * 128 + cc * 4;
    float4 bb = *(const float4*)&bias[ncol];
    #pragma unroll 4
    for (int rr = 0; rr < 16; rr++) {
        int row = (tid >> 5) * 16 + rr;
        size_t m = arow + row;
        float4 v = *(float4*)&stg[row * SPITCH + cc * 4];
        v.x += bb.x; v.y += bb.y; v.z += bb.z; v.w += bb.w;
        if (GELU_) {
            v.x = gelu_exact(v.x); v.y = gelu_exact(v.y);
            v.z = gelu_exact(v.z); v.w = gelu_exact(v.w);
        }
        if (RES_) {
            float4 rv = *(const float4*)&residual[m * N + ncol];
            v.x += rv.x; v.y += rv.y; v.z += rv.z; v.w += rv.w;
        }
        if (OUTF) *(float4*)&Cf[m * N + ncol] = v;
        if (OUTB) {
            __nv_bfloat16 h[4], l[4];
            split_bf16(v.x, h[0], l[0]); split_bf16(v.y, h[1], l[1]);
            split_bf16(v.z, h[2], l[2]); split_bf16(v.w, h[3], l[3]);
            size_t o = m * N + ncol;
            *(__nv_bfloat162*)&Chi[o]     = __nv_bfloat162(h[0], h[1]);
            *(__nv_bfloat162*)&Chi[o + 2] = __nv_bfloat162(h[2], h[3]);
            *(__nv_bfloat162*)&Clo[o]     = __nv_bfloat162(l[0], l[1]);
            *(__nv_bfloat162*)&Clo[o + 2] = __nv_bfloat162(l[2], l[3]);
        }
    }
}

// ----------------------------------------------------------------------------
// Flash-style causal attention, fp32; emits bf16 hi/lo for Wo GEMM.
// ----------------------------------------------------------------------------
#define APITCH 68

__global__ void __launch_bounds__(256) attn_kernel(const float* __restrict__ QKV,
                                                   __nv_bfloat16* __restrict__ Ohi,
                                                   __nv_bfloat16* __restrict__ Olo)
{
    extern __shared__ float sm[];
    float* Qs = sm;
    float* Ks = sm + 64 * APITCH;
    float* Vs = sm + 2 * 64 * APITCH;
    float* Ps = sm + 3 * 64 * APITCH;

    int qb = blockIdx.x;
    int bh = blockIdx.y;
    int b = bh >> 4, h = bh & 15;
    int tid = threadIdx.x;
    int r = tid >> 2;
    int q = tid & 3;

    const size_t base = (size_t)b * Sn * 3072 + (size_t)h * 64;

    for (int i = tid; i < 64 * 16; i += 256) {
        int rr = i >> 4, c4 = (i & 15) << 2;
        float4 v = *(const float4*)(QKV + base + (size_t)(qb * 64 + rr) * 3072 + c4);
        float* dst = &Qs[rr * APITCH + c4];
        dst[0] = v.x * 0.125f; dst[1] = v.y * 0.125f;
        dst[2] = v.z * 0.125f; dst[3] = v.w * 0.125f;
    }

    float o[16];
    #pragma unroll
    for (int j = 0; j < 16; j++) o[j] = 0.0f;
    float m_prev = -1e30f, l_prev = 0.0f;
    const int qg = qb * 64 + r;

    for (int kb = 0; kb <= qb; kb++) {
        __syncthreads();
        for (int i = tid; i < 64 * 16; i += 256) {
            int rr = i >> 4, c4 = (i & 15) << 2;
            size_t off = base + (size_t)(kb * 64 + rr) * 3072 + c4;
            *(float4*)&Ks[rr * APITCH + c4] = *(const float4*)(QKV + off + 1024);
            *(float4*)&Vs[rr * APITCH + c4] = *(const float4*)(QKV + off + 2048);
        }
        __syncthreads();

        float s[16];
        #pragma unroll
        for (int j = 0; j < 16; j++) s[j] = 0.0f;
        #pragma unroll 4
        for (int k4 = 0; k4 < 16; k4++) {
            float4 qv = *(const float4*)&Qs[r * APITCH + (k4 << 2)];
            #pragma unroll
            for (int j = 0; j < 16; j++) {
                float4 kv = *(const float4*)&Ks[(q * 16 + j) * APITCH + (k4 << 2)];
                s[j] += qv.x * kv.x + qv.y * kv.y + qv.z * kv.z + qv.w * kv.w;
            }
        }

        float mloc = -1e30f;
        #pragma unroll
        for (int j = 0; j < 16; j++) {
            int tg = kb * 64 + q * 16 + j;
            if (tg > qg) s[j] = -1e30f;
            mloc = fmaxf(mloc, s[j]);
        }
        mloc = fmaxf(mloc, __shfl_xor_sync(0xffffffffu, mloc, 1));
        mloc = fmaxf(mloc, __shfl_xor_sync(0xffffffffu, mloc, 2));

        float m_new = fmaxf(m_prev, mloc);
        float alpha = __expf(m_prev - m_new);

        float lsum = 0.0f;
        #pragma unroll
        for (int j = 0; j < 16; j++) {
            float p = __expf(s[j] - m_new);
            Ps[r * APITCH + q * 16 + j] = p;
            lsum += p;
        }
        lsum += __shfl_xor_sync(0xffffffffu, lsum, 1);
        lsum += __shfl_xor_sync(0xffffffffu, lsum, 2);

        l_prev = l_prev * alpha + lsum;
        m_prev = m_new;
        #pragma unroll
        for (int j = 0; j < 16; j++) o[j] *= alpha;

        __syncwarp();

        #pragma unroll 4
        for (int t = 0; t < 64; t++) {
            float pv = Ps[r * APITCH + t];
            const float* vrow = &Vs[t * APITCH + q * 16];
            float4 v0 = *(const float4*)(vrow + 0);
            float4 v1 = *(const float4*)(vrow + 4);
            float4 v2 = *(const float4*)(vrow + 8);
            float4 v3 = *(const float4*)(vrow + 12);
            o[0]  += pv * v0.x; o[1]  += pv * v0.y; o[2]  += pv * v0.z; o[3]  += pv * v0.w;
            o[4]  += pv * v1.x; o[5]  += pv * v1.y; o[6]  += pv * v1.z; o[7]  += pv * v1.w;
            o[8]  += pv * v2.x; o[9]  += pv * v2.y; o[10] += pv * v2.z; o[11] += pv * v2.w;
            o[12] += pv * v3.x; o[13] += pv * v3.y; o[14] += pv * v3.z; o[15] += pv * v3.w;
        }
    }

    float linv = 1.0f / l_prev;
    size_t ob = (size_t)(b * Sn + qb * 64 + r) * Dn + h * 64 + q * 16;
    #pragma unroll
    for (int j = 0; j < 16; j += 2) {
        float v0 = o[j] * linv, v1 = o[j + 1] * linv;
        __nv_bfloat16 h0, l0, h1, l1;
        split_bf16(v0, h0, l0); split_bf16(v1, h1, l1);
        *(__nv_bfloat162*)&Ohi[ob + j] = __nv_bfloat162(h0, h1);
        *(__nv_bfloat162*)&Olo[ob + j] = __nv_bfloat162(l0, l1);
    }
}

// ----------------------------------------------------------------------------
// Launch
// ----------------------------------------------------------------------------
extern "C" void kernel_launch(void* const* d_in, const int* in_sizes, int n_in,
                              void* d_out, int out_size)
{
    const float* x     = (const float*)d_in[0];
    const float* Wq    = (const float*)d_in[1];
    const float* Wk    = (const float*)d_in[2];
    const float* Wv    = (const float*)d_in[3];
    const float* bq    = (const float*)d_in[4];
    const float* bk    = (const float*)d_in[5];
    const float* bv    = (const float*)d_in[6];
    const float* Wo    = (const float*)d_in[7];
    const float* bo    = (const float*)d_in[8];
    const float* W1    = (const float*)d_in[9];
    const float* b1    = (const float*)d_in[10];
    const float* W2    = (const float*)d_in[11];
    const float* b2    = (const float*)d_in[12];
    const float* gamma = (const float*)d_in[13];
    const float* beta  = (const float*)d_in[14];
    float* out = (float*)d_out;

    float *qkv, *bp;
    __nv_bfloat16 *hAh, *hAl, *ath, *atl, *h1h, *h1l;
    __nv_bfloat16 *wqh, *wql, *woh, *wol, *w1h, *w1l, *w2h, *w2l;
    cudaGetSymbolAddress((void**)&qkv, g_qkv);
    cudaGetSymbolAddress((void**)&bp,  g_bp);
    cudaGetSymbolAddress((void**)&hAh, g_hA_hi); cudaGetSymbolAddress((void**)&hAl, g_hA_lo);
    cudaGetSymbolAddress((void**)&ath, g_at_hi); cudaGetSymbolAddress((void**)&atl, g_at_lo);
    cudaGetSymbolAddress((void**)&h1h, g_h1_hi); cudaGetSymbolAddress((void**)&h1l, g_h1_lo);
    cudaGetSymbolAddress((void**)&wqh, g_wqkvT_hi); cudaGetSymbolAddress((void**)&wql, g_wqkvT_lo);
    cudaGetSymbolAddress((void**)&woh, g_woT_hi);   cudaGetSymbolAddress((void**)&wol, g_woT_lo);
    cudaGetSymbolAddress((void**)&w1h, g_w1T_hi);   cudaGetSymbolAddress((void**)&w1l, g_w1T_lo);
    cudaGetSymbolAddress((void**)&w2h, g_w2T_hi);   cudaGetSymbolAddress((void**)&w2l, g_w2T_lo);

    cudaFuncSetAttribute(mma_gemm_kernel<false, false, true,  false>,
                         cudaFuncAttributeMaxDynamicSharedMemorySize, GEMM_SMEM);
    cudaFuncSetAttribute(mma_gemm_kernel<false, true,  true,  false>,
                         cudaFuncAttributeMaxDynamicSharedMemorySize, GEMM_SMEM);
    cudaFuncSetAttribute(mma_gemm_kernel<true,  false, false, true >,
                         cudaFuncAttributeMaxDynamicSharedMemorySize, GEMM_SMEM);

    // --- weight packing (transpose + bf16 split) ---
    dim3 tb(32, 8);
    transpose_pack_kernel<<<dim3(2, 32, 16), tb>>>(Wq, wqh, wql, Dn, HDn, (long long)Dn * HDn, 0,      Dn);
    transpose_pack_kernel<<<dim3(2, 32, 16), tb>>>(Wk, wqh, wql, Dn, HDn, (long long)Dn * HDn, Dn,     Dn);
    transpose_pack_kernel<<<dim3(2, 32, 16), tb>>>(Wv, wqh, wql, Dn, HDn, (long long)Dn * HDn, 2 * Dn, Dn);
    transpose_pack_kernel<<<dim3(32, 32, 1),  tb>>>(Wo, woh, wol, Dn, Dn, 0, 0, Dn);
    transpose_pack_kernel<<<dim3(128, 32, 1), tb>>>(W1, w1h, w1l, Dn, D4, 0, 0, Dn);
    transpose_pack_kernel<<<dim3(32, 128, 1), tb>>>(W2, w2h, w2l, D4, Dn, 0, 0, D4);
    bias_pack_kernel<<<12, 256>>>(bq, bk, bv, bp);

    // --- LN1 ---
    ln_kernel<<<Mrows, 256>>>(x, gamma, beta, hAh, hAl);

    // --- QKV GEMM ---
    mma_gemm_kernel<false, false, true, false><<<dim3(3 * Dn / 128, Mrows / 128), 256, GEMM_SMEM>>>(
        hAh, hAl, wqh, wql, bp, nullptr, qkv, nullptr, nullptr, 3 * Dn, Dn);

    // --- attention ---
    const int attn_smem = 4 * 64 * APITCH * (int)sizeof(float);
    cudaFuncSetAttribute(attn_kernel, cudaFuncAttributeMaxDynamicSharedMemorySize, attn_smem);
    attn_kernel<<<dim3(Sn / 64, Bn * Hn), 256, attn_smem>>>(qkv, ath, atl);

    // --- Wo GEMM + residual ---
    mma_gemm_kernel<false, true, true, false><<<dim3(Dn / 128, Mrows / 128), 256, GEMM_SMEM>>>(
        ath, atl, woh, wol, bo, x, out, nullptr, nullptr, Dn, Dn);

    // --- LN2 ---
    ln_kernel<<<Mrows, 256>>>(out, gamma, beta, hAh, hAl);

    // --- MLP1 + GELU ---
    mma_gemm_kernel<true, false, false, true><<<dim3(D4 / 128, Mrows / 128), 256, GEMM_SMEM>>>(
        hAh, hAl, w1h, w1l, b1, nullptr, nullptr, h1h, h1l, D4, Dn);

    // --- MLP2 + residual ---
    mma_gemm_kernel<false, true, true, false><<<dim3(Dn / 128, Mrows / 128), 256, GEMM_SMEM>>>(
        h1h, h1l, w2h, w2l, b2, out, out, nullptr, nullptr, Dn, D4);
}

// round 6
// speedup vs baseline: 1.0326x; 1.0326x over previous
#include <cuda_runtime.h>
#include <cuda_bf16.h>
#include <cstdint>
#include <math.h>

// ----------------------------------------------------------------------------
// Problem constants
// ----------------------------------------------------------------------------
#define Bn   4
#define Sn   2048
#define Dn   1024
#define Hn   16
#define HDn  64
#define Mrows (Bn*Sn)          // 8192
#define D4   (4*Dn)            // 4096

// ----------------------------------------------------------------------------
// Scratch (device globals -- no allocations allowed)
// ----------------------------------------------------------------------------
__device__ float         g_qkv  [(size_t)Mrows * 3 * Dn];
__device__ __nv_bfloat16 g_hA_hi[(size_t)Mrows * Dn];
__device__ __nv_bfloat16 g_hA_lo[(size_t)Mrows * Dn];
__device__ __nv_bfloat16 g_at_hi[(size_t)Mrows * Dn];
__device__ __nv_bfloat16 g_at_lo[(size_t)Mrows * Dn];
__device__ __nv_bfloat16 g_h1_hi[(size_t)Mrows * D4];
__device__ __nv_bfloat16 g_h1_lo[(size_t)Mrows * D4];
__device__ __nv_bfloat16 g_wqkvT_hi[(size_t)3 * Dn * Dn];
__device__ __nv_bfloat16 g_wqkvT_lo[(size_t)3 * Dn * Dn];
__device__ __nv_bfloat16 g_woT_hi[(size_t)Dn * Dn];
__device__ __nv_bfloat16 g_woT_lo[(size_t)Dn * Dn];
__device__ __nv_bfloat16 g_w1T_hi[(size_t)D4 * Dn];
__device__ __nv_bfloat16 g_w1T_lo[(size_t)D4 * Dn];
__device__ __nv_bfloat16 g_w2T_hi[(size_t)Dn * D4];
__device__ __nv_bfloat16 g_w2T_lo[(size_t)Dn * D4];
__device__ float         g_bp[3 * Dn];

__device__ __forceinline__ void split_bf16(float v, __nv_bfloat16& h, __nv_bfloat16& l) {
    h = __float2bfloat16(v);
    l = __float2bfloat16(v - __bfloat162float(h));
}

__device__ __forceinline__ uint32_t smem_u32(const void* p) {
    uint32_t a;
    asm("{ .reg .u64 t; cvta.to.shared.u64 t, %1; cvt.u32.u64 %0, t; }" : "=r"(a) : "l"(p));
    return a;
}
__device__ __forceinline__ void cp_async16(void* dst, const void* src) {
    asm volatile("cp.async.cg.shared.global [%0], [%1], 16;"
                 :: "r"(smem_u32(dst)), "l"(src) : "memory");
}
#define CP_COMMIT() asm volatile("cp.async.commit_group;" ::: "memory")
#define CP_WAIT(n)  asm volatile("cp.async.wait_group %0;" :: "n"(n) : "memory")

__device__ __forceinline__ void ldsm_x4(uint32_t* r, uint32_t a) {
    asm volatile("ldmatrix.sync.aligned.m8n8.x4.shared.b16 {%0,%1,%2,%3}, [%4];"
                 : "=r"(r[0]), "=r"(r[1]), "=r"(r[2]), "=r"(r[3]) : "r"(a));
}
__device__ __forceinline__ void mma16816(float* d, const uint32_t* a, const uint32_t* b) {
    asm volatile("mma.sync.aligned.m16n8k16.row.col.f32.bf16.bf16.f32 "
                 "{%0,%1,%2,%3}, {%4,%5,%6,%7}, {%8,%9}, {%0,%1,%2,%3};"
                 : "+f"(d[0]), "+f"(d[1]), "+f"(d[2]), "+f"(d[3])
                 : "r"(a[0]), "r"(a[1]), "r"(a[2]), "r"(a[3]), "r"(b[0]), "r"(b[1]));
}

// ----------------------------------------------------------------------------
// Transpose + bf16 split: src [Ks, Ns] fp32  ->  dst [Ns, Ks] hi/lo bf16 rows.
// ----------------------------------------------------------------------------
__global__ void transpose_pack_kernel(const float* __restrict__ src,
                                      __nv_bfloat16* __restrict__ dhi,
                                      __nv_bfloat16* __restrict__ dlo,
                                      int Ks, int Ns, long long src_zoff,
                                      int out_row_base, int out_stride)
{
    __shared__ float t[32][33];
    int z = blockIdx.z;
    src += (size_t)z * src_zoff;
    int n0 = blockIdx.x * 32, k0 = blockIdx.y * 32;
    int tx = threadIdx.x, ty = threadIdx.y;
    #pragma unroll
    for (int j = 0; j < 4; j++) {
        int k = k0 + ty + j * 8;
        t[ty + j * 8][tx] = src[(size_t)k * Ns + n0 + tx];
    }
    __syncthreads();
    #pragma unroll
    for (int j = 0; j < 4; j++) {
        int n = n0 + ty + j * 8;
        float v = t[tx][ty + j * 8];
        __nv_bfloat16 h, l; split_bf16(v, h, l);
        size_t o = (size_t)(out_row_base + z * Ns + n) * out_stride + k0 + tx;
        dhi[o] = h; dlo[o] = l;
    }
}

__global__ void bias_pack_kernel(const float* __restrict__ bq,
                                 const float* __restrict__ bk,
                                 const float* __restrict__ bv,
                                 float* __restrict__ bp)
{
    int idx = blockIdx.x * 256 + threadIdx.x;
    if (idx < 3 * Dn) {
        int w = idx >> 10, c = idx & 1023;
        bp[idx] = (w == 0 ? bq : w == 1 ? bk : bv)[c];
    }
}

// ----------------------------------------------------------------------------
// LayerNorm -> bf16 hi/lo. One block per row, 256 threads, 4 elems each.
// ----------------------------------------------------------------------------
__global__ void __launch_bounds__(256) ln_kernel(const float* __restrict__ X,
                                                 const float* __restrict__ gamma,
                                                 const float* __restrict__ beta,
                                                 __nv_bfloat16* __restrict__ Yhi,
                                                 __nv_bfloat16* __restrict__ Ylo)
{
    int row = blockIdx.x;
    int tid = threadIdx.x;
    float4 xv = ((const float4*)(X + (size_t)row * Dn))[tid];

    __shared__ float red[8];
    float s = xv.x + xv.y + xv.z + xv.w;
    #pragma unroll
    for (int o = 16; o > 0; o >>= 1) s += __shfl_xor_sync(0xffffffffu, s, o);
    if ((tid & 31) == 0) red[tid >> 5] = s;
    __syncthreads();
    float mu = (red[0]+red[1]+red[2]+red[3]+red[4]+red[5]+red[6]+red[7]) * (1.0f / Dn);
    __syncthreads();

    float dx = xv.x - mu, dy = xv.y - mu, dz = xv.z - mu, dw = xv.w - mu;
    float sq = dx*dx + dy*dy + dz*dz + dw*dw;
    #pragma unroll
    for (int o = 16; o > 0; o >>= 1) sq += __shfl_xor_sync(0xffffffffu, sq, o);
    if ((tid & 31) == 0) red[tid >> 5] = sq;
    __syncthreads();
    float var = (red[0]+red[1]+red[2]+red[3]+red[4]+red[5]+red[6]+red[7]) * (1.0f / Dn);
    float inv = rsqrtf(var + 1e-5f);

    float4 gv = ((const float4*)gamma)[tid];
    float4 bv = ((const float4*)beta)[tid];
    float o0 = dx*inv*gv.x + bv.x, o1 = dy*inv*gv.y + bv.y;
    float o2 = dz*inv*gv.z + bv.z, o3 = dw*inv*gv.w + bv.w;

    __nv_bfloat16 h[4], l[4];
    split_bf16(o0, h[0], l[0]); split_bf16(o1, h[1], l[1]);
    split_bf16(o2, h[2], l[2]); split_bf16(o3, h[3], l[3]);
    size_t off = (size_t)row * Dn + tid * 4;
    *(__nv_bfloat162*)&Yhi[off]     = __nv_bfloat162(h[0], h[1]);
    *(__nv_bfloat162*)&Yhi[off + 2] = __nv_bfloat162(h[2], h[3]);
    *(__nv_bfloat162*)&Ylo[off]     = __nv_bfloat162(l[0], l[1]);
    *(__nv_bfloat162*)&Ylo[off + 2] = __nv_bfloat162(l[2], l[3]);
}

// ----------------------------------------------------------------------------
// Raw mma.sync bf16 GEMM, 3-stage cp.async, BK=64, 8 warps, warp tile 64x32.
// C[128x128 fp32] = A[128,K] . B^T, hi/lo 3-pass (Ah.Bh + Ah.Bl + Al.Bh).
// Fragments via ldmatrix; Ah fragments reused across Bh/Bl passes.
// ----------------------------------------------------------------------------
__device__ __forceinline__ float gelu_exact(float v) {
    return 0.5f * v * (1.0f + erff(v * 0.70710678118654752f));
}

#define BK     64
#define KPITCH 72                    // bf16/row (64 + 8 pad) = 144B pitch
#define TILEB  (128 * KPITCH * 2)    // 18432 B per matrix tile
#define STAGEB (4 * TILEB)           // 73728 B per stage (Ah, Al, Bh, Bl)
#define NSTAGE 3
#define GEMM_SMEM (NSTAGE * STAGEB)  // 221184 B
#define SPITCH 132                   // fp32 staging pitch

template <bool GELU_, bool RES_, bool OUTF, bool OUTB>
__global__ void __launch_bounds__(256) mma_gemm_kernel(
    const __nv_bfloat16* __restrict__ Ahi, const __nv_bfloat16* __restrict__ Alo,
    const __nv_bfloat16* __restrict__ Bhi, const __nv_bfloat16* __restrict__ Blo,
    const float* __restrict__ bias, const float* __restrict__ residual,
    float* __restrict__ Cf, __nv_bfloat16* __restrict__ Chi, __nv_bfloat16* __restrict__ Clo,
    int N, int K)
{
    extern __shared__ __align__(128) char smem[];
    float* stg = (float*)smem;   // epilogue staging overlays tiles

    const int tid = threadIdx.x;
    const int wid = tid >> 5;
    const int lane = tid & 31;
    const int wm = wid >> 2;          // 0..1  (64-row band)
    const int wn = wid & 3;           // 0..3  (32-col band)
    const int bx = blockIdx.x, by = blockIdx.y;

    const size_t arow = (size_t)by * 128;
    const size_t brow = (size_t)bx * 128;

    auto load_chunk = [&](int kc, int st) {
        char* base = smem + st * STAGEB;
        __nv_bfloat16* Ah_s = (__nv_bfloat16*)(base + 0 * TILEB);
        __nv_bfloat16* Al_s = (__nv_bfloat16*)(base + 1 * TILEB);
        __nv_bfloat16* Bh_s = (__nv_bfloat16*)(base + 2 * TILEB);
        __nv_bfloat16* Bl_s = (__nv_bfloat16*)(base + 3 * TILEB);
        #pragma unroll
        for (int i = 0; i < 4; i++) {
            int idx = tid + i * 256;
            int row = idx >> 3, c = idx & 7;
            size_t ao = (arow + row) * (size_t)K + kc * BK + c * 8;
            size_t bo = (brow + row) * (size_t)K + kc * BK + c * 8;
            int so = row * KPITCH + c * 8;
            cp_async16(&Ah_s[so], Ahi + ao);
            cp_async16(&Al_s[so], Alo + ao);
            cp_async16(&Bh_s[so], Bhi + bo);
            cp_async16(&Bl_s[so], Blo + bo);
        }
    };

    // accumulators: 4 m-tiles x 4 n8-tiles x 4 floats
    float acc[4][4][4];
    #pragma unroll
    for (int i = 0; i < 4; i++)
        #pragma unroll
        for (int n = 0; n < 4; n++)
            #pragma unroll
            for (int e = 0; e < 4; e++) acc[i][n][e] = 0.0f;

    // ldmatrix lane-address components
    const int a_r  = wm * 64 + (lane & 15);     // row within 128 (+i*16)
    const int a_k  = (lane >> 4) << 3;          // 0 or 8 (k half)
    const int b_r  = wn * 32 + ((lane >> 4) << 3) + (lane & 7);   // row within 128 (+g*16)
    const int b_k  = ((lane >> 3) & 1) << 3;    // 0 or 8

    const int nk = K / BK;
    load_chunk(0, 0); CP_COMMIT();
    load_chunk(1, 1); CP_COMMIT();

    for (int kc = 0; kc < nk; kc++) {
        const int st = kc % NSTAGE;
        if (kc + 2 < nk) { load_chunk(kc + 2, (kc + 2) % NSTAGE); CP_COMMIT(); }
        if      (kc + 2 < nk) CP_WAIT(2);
        else if (kc + 1 < nk) CP_WAIT(1);
        else                  CP_WAIT(0);
        __syncthreads();

        char* base = smem + st * STAGEB;
        const uint32_t uAh = smem_u32(base + 0 * TILEB);
        const uint32_t uAl = smem_u32(base + 1 * TILEB);
        const uint32_t uBh = smem_u32(base + 2 * TILEB);
        const uint32_t uBl = smem_u32(base + 3 * TILEB);

        #pragma unroll
        for (int ks = 0; ks < BK / 16; ks++) {
            uint32_t ah[4][4], al[4][4], bh[2][4], bl[2][4];
            const int kof = ks * 16;
            #pragma unroll
            for (int i = 0; i < 4; i++)
                ldsm_x4(ah[i], uAh + (uint32_t)(((a_r + i * 16) * KPITCH + kof + a_k) * 2));
            #pragma unroll
            for (int g = 0; g < 2; g++)
                ldsm_x4(bh[g], uBh + (uint32_t)(((b_r + g * 16) * KPITCH + kof + b_k) * 2));
            #pragma unroll
            for (int g = 0; g < 2; g++)
                ldsm_x4(bl[g], uBl + (uint32_t)(((b_r + g * 16) * KPITCH + kof + b_k) * 2));
            #pragma unroll
            for (int i = 0; i < 4; i++)
                ldsm_x4(al[i], uAl + (uint32_t)(((a_r + i * 16) * KPITCH + kof + a_k) * 2));

            // pass 1: Ah.Bh
            #pragma unroll
            for (int i = 0; i < 4; i++)
                #pragma unroll
                for (int n = 0; n < 4; n++)
                    mma16816(acc[i][n], ah[i], &bh[n >> 1][(n & 1) * 2]);
            // pass 2: Ah.Bl
            #pragma unroll
            for (int i = 0; i < 4; i++)
                #pragma unroll
                for (int n = 0; n < 4; n++)
                    mma16816(acc[i][n], ah[i], &bl[n >> 1][(n & 1) * 2]);
            // pass 3: Al.Bh
            #pragma unroll
            for (int i = 0; i < 4; i++)
                #pragma unroll
                for (int n = 0; n < 4; n++)
                    mma16816(acc[i][n], al[i], &bh[n >> 1][(n & 1) * 2]);
        }
        __syncthreads();
    }

    // Stage accumulators to smem (mma acc layout), then fused epilogue.
    const int c_r = lane >> 2;           // 0..7
    const int c_c = (lane & 3) << 1;     // 0,2,4,6
    #pragma unroll
    for (int i = 0; i < 4; i++)
        #pragma unroll
        for (int n = 0; n < 4; n++) {
            int r0 = wm * 64 + i * 16 + c_r;
            int c0 = wn * 32 + n * 8 + c_c;
            stg[r0 * SPITCH + c0]           = acc[i][n][0];
            stg[r0 * SPITCH + c0 + 1]       = acc[i][n][1];
            stg[(r0 + 8) * SPITCH + c0]     = acc[i][n][2];
            stg[(r0 + 8) * SPITCH + c0 + 1] = acc[i][n][3];
        }
    __syncthreads();

    const int cc = tid & 31;
    const int ncol = bx * 128 + cc * 4;
    float4 bb = *(const float4*)&bias[ncol];
    #pragma unroll 4
    for (int rr = 0; rr < 16; rr++) {
        int row = (tid >> 5) * 16 + rr;
        size_t m = arow + row;
        float4 v = *(float4*)&stg[row * SPITCH + cc * 4];
        v.x += bb.x; v.y += bb.y; v.z += bb.z; v.w += bb.w;
        if (GELU_) {
            v.x = gelu_exact(v.x); v.y = gelu_exact(v.y);
            v.z = gelu_exact(v.z); v.w = gelu_exact(v.w);
        }
        if (RES_) {
            float4 rv = *(const float4*)&residual[m * N + ncol];
            v.x += rv.x; v.y += rv.y; v.z += rv.z; v.w += rv.w;
        }
        if (OUTF) *(float4*)&Cf[m * N + ncol] = v;
        if (OUTB) {
            __nv_bfloat16 h[4], l[4];
            split_bf16(v.x, h[0], l[0]); split_bf16(v.y, h[1], l[1]);
            split_bf16(v.z, h[2], l[2]); split_bf16(v.w, h[3], l[3]);
            size_t o = m * N + ncol;
            *(__nv_bfloat162*)&Chi[o]     = __nv_bfloat162(h[0], h[1]);
            *(__nv_bfloat162*)&Chi[o + 2] = __nv_bfloat162(h[2], h[3]);
            *(__nv_bfloat162*)&Clo[o]     = __nv_bfloat162(l[0], l[1]);
            *(__nv_bfloat162*)&Clo[o + 2] = __nv_bfloat162(l[2], l[3]);
        }
    }
}

// ----------------------------------------------------------------------------
// Flash-style causal attention, fp32; emits bf16 hi/lo for Wo GEMM.
// ----------------------------------------------------------------------------
#define APITCH 68

__global__ void __launch_bounds__(256) attn_kernel(const float* __restrict__ QKV,
                                                   __nv_bfloat16* __restrict__ Ohi,
                                                   __nv_bfloat16* __restrict__ Olo)
{
    extern __shared__ float sm[];
    float* Qs = sm;
    float* Ks = sm + 64 * APITCH;
    float* Vs = sm + 2 * 64 * APITCH;
    float* Ps = sm + 3 * 64 * APITCH;

    int qb = blockIdx.x;
    int bh = blockIdx.y;
    int b = bh >> 4, h = bh & 15;
    int tid = threadIdx.x;
    int r = tid >> 2;
    int q = tid & 3;

    const size_t base = (size_t)b * Sn * 3072 + (size_t)h * 64;

    for (int i = tid; i < 64 * 16; i += 256) {
        int rr = i >> 4, c4 = (i & 15) << 2;
        float4 v = *(const float4*)(QKV + base + (size_t)(qb * 64 + rr) * 3072 + c4);
        float* dst = &Qs[rr * APITCH + c4];
        dst[0] = v.x * 0.125f; dst[1] = v.y * 0.125f;
        dst[2] = v.z * 0.125f; dst[3] = v.w * 0.125f;
    }

    float o[16];
    #pragma unroll
    for (int j = 0; j < 16; j++) o[j] = 0.0f;
    float m_prev = -1e30f, l_prev = 0.0f;
    const int qg = qb * 64 + r;

    for (int kb = 0; kb <= qb; kb++) {
        __syncthreads();
        for (int i = tid; i < 64 * 16; i += 256) {
            int rr = i >> 4, c4 = (i & 15) << 2;
            size_t off = base + (size_t)(kb * 64 + rr) * 3072 + c4;
            *(float4*)&Ks[rr * APITCH + c4] = *(const float4*)(QKV + off + 1024);
            *(float4*)&Vs[rr * APITCH + c4] = *(const float4*)(QKV + off + 2048);
        }
        __syncthreads();

        float s[16];
        #pragma unroll
        for (int j = 0; j < 16; j++) s[j] = 0.0f;
        #pragma unroll 4
        for (int k4 = 0; k4 < 16; k4++) {
            float4 qv = *(const float4*)&Qs[r * APITCH + (k4 << 2)];
            #pragma unroll
            for (int j = 0; j < 16; j++) {
                float4 kv = *(const float4*)&Ks[(q * 16 + j) * APITCH + (k4 << 2)];
                s[j] += qv.x * kv.x + qv.y * kv.y + qv.z * kv.z + qv.w * kv.w;
            }
        }

        float mloc = -1e30f;
        #pragma unroll
        for (int j = 0; j < 16; j++) {
            int tg = kb * 64 + q * 16 + j;
            if (tg > qg) s[j] = -1e30f;
            mloc = fmaxf(mloc, s[j]);
        }
        mloc = fmaxf(mloc, __shfl_xor_sync(0xffffffffu, mloc, 1));
        mloc = fmaxf(mloc, __shfl_xor_sync(0xffffffffu, mloc, 2));

        float m_new = fmaxf(m_prev, mloc);
        float alpha = __expf(m_prev - m_new);

        float lsum = 0.0f;
        #pragma unroll
        for (int j = 0; j < 16; j++) {
            float p = __expf(s[j] - m_new);
            Ps[r * APITCH + q * 16 + j] = p;
            lsum += p;
        }
        lsum += __shfl_xor_sync(0xffffffffu, lsum, 1);
        lsum += __shfl_xor_sync(0xffffffffu, lsum, 2);

        l_prev = l_prev * alpha + lsum;
        m_prev = m_new;
        #pragma unroll
        for (int j = 0; j < 16; j++) o[j] *= alpha;

        __syncwarp();

        #pragma unroll 4
        for (int t = 0; t < 64; t++) {
            float pv = Ps[r * APITCH + t];
            const float* vrow = &Vs[t * APITCH + q * 16];
            float4 v0 = *(const float4*)(vrow + 0);
            float4 v1 = *(const float4*)(vrow + 4);
            float4 v2 = *(const float4*)(vrow + 8);
            float4 v3 = *(const float4*)(vrow + 12);
            o[0]  += pv * v0.x; o[1]  += pv * v0.y; o[2]  += pv * v0.z; o[3]  += pv * v0.w;
            o[4]  += pv * v1.x; o[5]  += pv * v1.y; o[6]  += pv * v1.z; o[7]  += pv * v1.w;
            o[8]  += pv * v2.x; o[9]  += pv * v2.y; o[10] += pv * v2.z; o[11] += pv * v2.w;
            o[12] += pv * v3.x; o[13] += pv * v3.y; o[14] += pv * v3.z; o[15] += pv * v3.w;
        }
    }

    float linv = 1.0f / l_prev;
    size_t ob = (size_t)(b * Sn + qb * 64 + r) * Dn + h * 64 + q * 16;
    #pragma unroll
    for (int j = 0; j < 16; j += 2) {
        float v0 = o[j] * linv, v1 = o[j + 1] * linv;
        __nv_bfloat16 h0, l0, h1, l1;
        split_bf16(v0, h0, l0); split_bf16(v1, h1, l1);
        *(__nv_bfloat162*)&Ohi[ob + j] = __nv_bfloat162(h0, h1);
        *(__nv_bfloat162*)&Olo[ob + j] = __nv_bfloat162(l0, l1);
    }
}

// ----------------------------------------------------------------------------
// Launch (ordered so launch index 5 == QKV GEMM for ncu -s 5 -c 1)
// ----------------------------------------------------------------------------
extern "C" void kernel_launch(void* const* d_in, const int* in_sizes, int n_in,
                              void* d_out, int out_size)
{
    const float* x     = (const float*)d_in[0];
    const float* Wq    = (const float*)d_in[1];
    const float* Wk    = (const float*)d_in[2];
    const float* Wv    = (const float*)d_in[3];
    const float* bq    = (const float*)d_in[4];
    const float* bk    = (const float*)d_in[5];
    const float* bv    = (const float*)d_in[6];
    const float* Wo    = (const float*)d_in[7];
    const float* bo    = (const float*)d_in[8];
    const float* W1    = (const float*)d_in[9];
    const float* b1    = (const float*)d_in[10];
    const float* W2    = (const float*)d_in[11];
    const float* b2    = (const float*)d_in[12];
    const float* gamma = (const float*)d_in[13];
    const float* beta  = (const float*)d_in[14];
    float* out = (float*)d_out;

    float *qkv, *bp;
    __nv_bfloat16 *hAh, *hAl, *ath, *atl, *h1h, *h1l;
    __nv_bfloat16 *wqh, *wql, *woh, *wol, *w1h, *w1l, *w2h, *w2l;
    cudaGetSymbolAddress((void**)&qkv, g_qkv);
    cudaGetSymbolAddress((void**)&bp,  g_bp);
    cudaGetSymbolAddress((void**)&hAh, g_hA_hi); cudaGetSymbolAddress((void**)&hAl, g_hA_lo);
    cudaGetSymbolAddress((void**)&ath, g_at_hi); cudaGetSymbolAddress((void**)&atl, g_at_lo);
    cudaGetSymbolAddress((void**)&h1h, g_h1_hi); cudaGetSymbolAddress((void**)&h1l, g_h1_lo);
    cudaGetSymbolAddress((void**)&wqh, g_wqkvT_hi); cudaGetSymbolAddress((void**)&wql, g_wqkvT_lo);
    cudaGetSymbolAddress((void**)&woh, g_woT_hi);   cudaGetSymbolAddress((void**)&wol, g_woT_lo);
    cudaGetSymbolAddress((void**)&w1h, g_w1T_hi);   cudaGetSymbolAddress((void**)&w1l, g_w1T_lo);
    cudaGetSymbolAddress((void**)&w2h, g_w2T_hi);   cudaGetSymbolAddress((void**)&w2l, g_w2T_lo);

    cudaFuncSetAttribute(mma_gemm_kernel<false, false, true,  false>,
                         cudaFuncAttributeMaxDynamicSharedMemorySize, GEMM_SMEM);
    cudaFuncSetAttribute(mma_gemm_kernel<false, true,  true,  false>,
                         cudaFuncAttributeMaxDynamicSharedMemorySize, GEMM_SMEM);
    cudaFuncSetAttribute(mma_gemm_kernel<true,  false, false, true >,
                         cudaFuncAttributeMaxDynamicSharedMemorySize, GEMM_SMEM);

    dim3 tb(32, 8);
    // launches 0-4: QKV weight packs, bias pack, LN1
    transpose_pack_kernel<<<dim3(2, 32, 16), tb>>>(Wq, wqh, wql, Dn, HDn, (long long)Dn * HDn, 0,      Dn);
    transpose_pack_kernel<<<dim3(2, 32, 16), tb>>>(Wk, wqh, wql, Dn, HDn, (long long)Dn * HDn, Dn,     Dn);
    transpose_pack_kernel<<<dim3(2, 32, 16), tb>>>(Wv, wqh, wql, Dn, HDn, (long long)Dn * HDn, 2 * Dn, Dn);
    bias_pack_kernel<<<12, 256>>>(bq, bk, bv, bp);
    ln_kernel<<<Mrows, 256>>>(x, gamma, beta, hAh, hAl);

    // launch 5: QKV GEMM  (ncu -s 5 -c 1 captures this)
    mma_gemm_kernel<false, false, true, false><<<dim3(3 * Dn / 128, Mrows / 128), 256, GEMM_SMEM>>>(
        hAh, hAl, wqh, wql, bp, nullptr, qkv, nullptr, nullptr, 3 * Dn, Dn);

    // attention
    const int attn_smem = 4 * 64 * APITCH * (int)sizeof(float);
    cudaFuncSetAttribute(attn_kernel, cudaFuncAttributeMaxDynamicSharedMemorySize, attn_smem);
    attn_kernel<<<dim3(Sn / 64, Bn * Hn), 256, attn_smem>>>(qkv, ath, atl);

    // Wo pack + GEMM + residual
    transpose_pack_kernel<<<dim3(32, 32, 1),  tb>>>(Wo, woh, wol, Dn, Dn, 0, 0, Dn);
    mma_gemm_kernel<false, true, true, false><<<dim3(Dn / 128, Mrows / 128), 256, GEMM_SMEM>>>(
        ath, atl, woh, wol, bo, x, out, nullptr, nullptr, Dn, Dn);

    // LN2
    ln_kernel<<<Mrows, 256>>>(out, gamma, beta, hAh, hAl);

    // W1 pack + MLP1 + GELU
    transpose_pack_kernel<<<dim3(128, 32, 1), tb>>>(W1, w1h, w1l, Dn, D4, 0, 0, Dn);
    mma_gemm_kernel<true, false, false, true><<<dim3(D4 / 128, Mrows / 128), 256, GEMM_SMEM>>>(
        hAh, hAl, w1h, w1l, b1, nullptr, nullptr, h1h, h1l, D4, Dn);

    // W2 pack + MLP2 + residual
    transpose_pack_kernel<<<dim3(32, 128, 1), tb>>>(W2, w2h, w2l, D4, Dn, 0, 0, D4);
    mma_gemm_kernel<false, true, true, false><<<dim3(Dn / 128, Mrows / 128), 256, GEMM_SMEM>>>(
        h1h, h1l, w2h, w2l, b2, out, out, nullptr, nullptr, Dn, D4);
}

// round 8
// speedup vs baseline: 1.1990x; 1.1612x over previous
#include <cuda_runtime.h>
#include <cuda_fp16.h>
#include <cstdint>
#include <math.h>

// ----------------------------------------------------------------------------
// Problem constants
// ----------------------------------------------------------------------------
#define Bn   4
#define Sn   2048
#define Dn   1024
#define Hn   16
#define HDn  64
#define Mrows (Bn*Sn)          // 8192
#define D4   (4*Dn)            // 4096

// ----------------------------------------------------------------------------
// Scratch (device globals -- no allocations allowed)
// ----------------------------------------------------------------------------
__device__ float  g_qkv  [(size_t)Mrows * 3 * Dn];
__device__ __half g_hA   [(size_t)Mrows * Dn];
__device__ __half g_at   [(size_t)Mrows * Dn];
__device__ __half g_h1   [(size_t)Mrows * D4];
__device__ __half g_wqkvT[(size_t)3 * Dn * Dn];
__device__ __half g_woT  [(size_t)Dn * Dn];
__device__ __half g_w1T  [(size_t)D4 * Dn];
__device__ __half g_w2T  [(size_t)Dn * D4];
__device__ float  g_bp[3 * Dn];

__device__ __forceinline__ uint32_t smem_u32(const void* p) {
    uint32_t a;
    asm("{ .reg .u64 t; cvta.to.shared.u64 t, %1; cvt.u32.u64 %0, t; }" : "=r"(a) : "l"(p));
    return a;
}
__device__ __forceinline__ void cp_async16(void* dst, const void* src) {
    asm volatile("cp.async.cg.shared.global [%0], [%1], 16;"
                 :: "r"(smem_u32(dst)), "l"(src) : "memory");
}
#define CP_COMMIT() asm volatile("cp.async.commit_group;" ::: "memory")
#define CP_WAIT(n)  asm volatile("cp.async.wait_group %0;" :: "n"(n) : "memory")

__device__ __forceinline__ void ldsm_x4(uint32_t* r, uint32_t a) {
    asm volatile("ldmatrix.sync.aligned.m8n8.x4.shared.b16 {%0,%1,%2,%3}, [%4];"
                 : "=r"(r[0]), "=r"(r[1]), "=r"(r[2]), "=r"(r[3]) : "r"(a));
}
__device__ __forceinline__ void mma16816(float* d, const uint32_t* a, const uint32_t* b) {
    asm volatile("mma.sync.aligned.m16n8k16.row.col.f32.f16.f16.f32 "
                 "{%0,%1,%2,%3}, {%4,%5,%6,%7}, {%8,%9}, {%0,%1,%2,%3};"
                 : "+f"(d[0]), "+f"(d[1]), "+f"(d[2]), "+f"(d[3])
                 : "r"(a[0]), "r"(a[1]), "r"(a[2]), "r"(a[3]), "r"(b[0]), "r"(b[1]));
}

// ----------------------------------------------------------------------------
// Transpose + fp16 pack: src [Ks, Ns] fp32 -> dst [Ns, Ks] fp16 rows.
// ----------------------------------------------------------------------------
__global__ void transpose_pack_kernel(const float* __restrict__ src,
                                      __half* __restrict__ dst,
                                      int Ks, int Ns, long long src_zoff,
                                      int out_row_base, int out_stride)
{
    __shared__ float t[32][33];
    int z = blockIdx.z;
    src += (size_t)z * src_zoff;
    int n0 = blockIdx.x * 32, k0 = blockIdx.y * 32;
    int tx = threadIdx.x, ty = threadIdx.y;
    #pragma unroll
    for (int j = 0; j < 4; j++) {
        int k = k0 + ty + j * 8;
        t[ty + j * 8][tx] = src[(size_t)k * Ns + n0 + tx];
    }
    __syncthreads();
    #pragma unroll
    for (int j = 0; j < 4; j++) {
        int n = n0 + ty + j * 8;
        size_t o = (size_t)(out_row_base + z * Ns + n) * out_stride + k0 + tx;
        dst[o] = __float2half_rn(t[tx][ty + j * 8]);
    }
}

__global__ void bias_pack_kernel(const float* __restrict__ bq,
                                 const float* __restrict__ bk,
                                 const float* __restrict__ bv,
                                 float* __restrict__ bp)
{
    int idx = blockIdx.x * 256 + threadIdx.x;
    if (idx < 3 * Dn) {
        int w = idx >> 10, c = idx & 1023;
        bp[idx] = (w == 0 ? bq : w == 1 ? bk : bv)[c];
    }
}

// ----------------------------------------------------------------------------
// LayerNorm -> fp16. One block per row, 256 threads, 4 elems each.
// ----------------------------------------------------------------------------
__global__ void __launch_bounds__(256) ln_kernel(const float* __restrict__ X,
                                                 const float* __restrict__ gamma,
                                                 const float* __restrict__ beta,
                                                 __half* __restrict__ Y)
{
    int row = blockIdx.x;
    int tid = threadIdx.x;
    float4 xv = ((const float4*)(X + (size_t)row * Dn))[tid];

    __shared__ float red[8];
    float s = xv.x + xv.y + xv.z + xv.w;
    #pragma unroll
    for (int o = 16; o > 0; o >>= 1) s += __shfl_xor_sync(0xffffffffu, s, o);
    if ((tid & 31) == 0) red[tid >> 5] = s;
    __syncthreads();
    float mu = (red[0]+red[1]+red[2]+red[3]+red[4]+red[5]+red[6]+red[7]) * (1.0f / Dn);
    __syncthreads();

    float dx = xv.x - mu, dy = xv.y - mu, dz = xv.z - mu, dw = xv.w - mu;
    float sq = dx*dx + dy*dy + dz*dz + dw*dw;
    #pragma unroll
    for (int o = 16; o > 0; o >>= 1) sq += __shfl_xor_sync(0xffffffffu, sq, o);
    if ((tid & 31) == 0) red[tid >> 5] = sq;
    __syncthreads();
    float var = (red[0]+red[1]+red[2]+red[3]+red[4]+red[5]+red[6]+red[7]) * (1.0f / Dn);
    float inv = rsqrtf(var + 1e-5f);

    float4 gv = ((const float4*)gamma)[tid];
    float4 bv = ((const float4*)beta)[tid];
    float o0 = dx*inv*gv.x + bv.x, o1 = dy*inv*gv.y + bv.y;
    float o2 = dz*inv*gv.z + bv.z, o3 = dw*inv*gv.w + bv.w;

    size_t off = (size_t)row * Dn + tid * 4;
    *(__half2*)&Y[off]     = __floats2half2_rn(o0, o1);
    *(__half2*)&Y[off + 2] = __floats2half2_rn(o2, o3);
}

// ----------------------------------------------------------------------------
// Raw mma.sync fp16 single-pass GEMM, 3-stage cp.async, BK=64, 8 warps,
// warp tile 64x32. C[128x128 fp32] = A[128,K] . B^T.
// ----------------------------------------------------------------------------
__device__ __forceinline__ float gelu_exact(float v) {
    return 0.5f * v * (1.0f + erff(v * 0.70710678118654752f));
}

#define BK     64
#define KPITCH 72                    // fp16/row (64 + 8 pad) = 144B pitch
#define TILEB  (128 * KPITCH * 2)    // 18432 B per matrix tile
#define STAGEB (2 * TILEB)           // 36864 B per stage (A, B)
#define NSTAGE 3
#define GEMM_SMEM (NSTAGE * STAGEB)  // 110592 B
#define SPITCH 132                   // fp32 staging pitch (67584 B, fits)

template <bool GELU_, bool RES_, bool OUTF, bool OUTB>
__global__ void __launch_bounds__(256) mma_gemm_kernel(
    const __half* __restrict__ A, const __half* __restrict__ B,
    const float* __restrict__ bias, const float* __restrict__ residual,
    float* __restrict__ Cf, __half* __restrict__ Ch,
    int N, int K)
{
    extern __shared__ __align__(128) char smem[];
    float* stg = (float*)smem;   // epilogue staging overlays tiles

    const int tid = threadIdx.x;
    const int wid = tid >> 5;
    const int lane = tid & 31;
    const int wm = wid >> 2;          // 0..1  (64-row band)
    const int wn = wid & 3;           // 0..3  (32-col band)
    const int bx = blockIdx.x, by = blockIdx.y;

    const size_t arow = (size_t)by * 128;
    const size_t brow = (size_t)bx * 128;

    auto load_chunk = [&](int kc, int st) {
        char* base = smem + st * STAGEB;
        __half* A_s = (__half*)(base);
        __half* B_s = (__half*)(base + TILEB);
        #pragma unroll
        for (int i = 0; i < 4; i++) {
            int idx = tid + i * 256;
            int row = idx >> 3, c = idx & 7;
            size_t ao = (arow + row) * (size_t)K + kc * BK + c * 8;
            size_t bo = (brow + row) * (size_t)K + kc * BK + c * 8;
            int so = row * KPITCH + c * 8;
            cp_async16(&A_s[so], A + ao);
            cp_async16(&B_s[so], B + bo);
        }
    };

    float acc[4][4][4];
    #pragma unroll
    for (int i = 0; i < 4; i++)
        #pragma unroll
        for (int n = 0; n < 4; n++)
            #pragma unroll
            for (int e = 0; e < 4; e++) acc[i][n][e] = 0.0f;

    const int a_r  = wm * 64 + (lane & 15);
    const int a_k  = (lane >> 4) << 3;
    const int b_r  = wn * 32 + ((lane >> 4) << 3) + (lane & 7);
    const int b_k  = ((lane >> 3) & 1) << 3;

    const int nk = K / BK;
    load_chunk(0, 0); CP_COMMIT();
    load_chunk(1, 1); CP_COMMIT();

    for (int kc = 0; kc < nk; kc++) {
        const int st = kc % NSTAGE;
        if (kc + 2 < nk) { load_chunk(kc + 2, (kc + 2) % NSTAGE); CP_COMMIT(); }
        if      (kc + 2 < nk) CP_WAIT(2);
        else if (kc + 1 < nk) CP_WAIT(1);
        else                  CP_WAIT(0);
        __syncthreads();

        char* base = smem + st * STAGEB;
        const uint32_t uA = smem_u32(base);
        const uint32_t uB = smem_u32(base + TILEB);

        #pragma unroll
        for (int ks = 0; ks < BK / 16; ks++) {
            uint32_t a[4][4], b[2][4];
            const int kof = ks * 16;
            #pragma unroll
            for (int i = 0; i < 4; i++)
                ldsm_x4(a[i], uA + (uint32_t)(((a_r + i * 16) * KPITCH + kof + a_k) * 2));
            #pragma unroll
            for (int g = 0; g < 2; g++)
                ldsm_x4(b[g], uB + (uint32_t)(((b_r + g * 16) * KPITCH + kof + b_k) * 2));
            #pragma unroll
            for (int i = 0; i < 4; i++)
                #pragma unroll
                for (int n = 0; n < 4; n++)
                    mma16816(acc[i][n], a[i], &b[n >> 1][(n & 1) * 2]);
        }
        __syncthreads();
    }

    // Stage accumulators to smem, fused epilogue to GMEM.
    const int c_r = lane >> 2;
    const int c_c = (lane & 3) << 1;
    #pragma unroll
    for (int i = 0; i < 4; i++)
        #pragma unroll
        for (int n = 0; n < 4; n++) {
            int r0 = wm * 64 + i * 16 + c_r;
            int c0 = wn * 32 + n * 8 + c_c;
            stg[r0 * SPITCH + c0]           = acc[i][n][0];
            stg[r0 * SPITCH + c0 + 1]       = acc[i][n][1];
            stg[(r0 + 8) * SPITCH + c0]     = acc[i][n][2];
            stg[(r0 + 8) * SPITCH + c0 + 1] = acc[i][n][3];
        }
    __syncthreads();

    const int cc = tid & 31;
    const int ncol = bx * 128 + cc * 4;
    float4 bb = *(const float4*)&bias[ncol];
    #pragma unroll 4
    for (int rr = 0; rr < 16; rr++) {
        int row = (tid >> 5) * 16 + rr;
        size_t m = arow + row;
        float4 v = *(float4*)&stg[row * SPITCH + cc * 4];
        v.x += bb.x; v.y += bb.y; v.z += bb.z; v.w += bb.w;
        if (GELU_) {
            v.x = gelu_exact(v.x); v.y = gelu_exact(v.y);
            v.z = gelu_exact(v.z); v.w = gelu_exact(v.w);
        }
        if (RES_) {
            float4 rv = *(const float4*)&residual[m * N + ncol];
            v.x += rv.x; v.y += rv.y; v.z += rv.z; v.w += rv.w;
        }
        if (OUTF) *(float4*)&Cf[m * N + ncol] = v;
        if (OUTB) {
            size_t o = m * N + ncol;
            *(__half2*)&Ch[o]     = __floats2half2_rn(v.x, v.y);
            *(__half2*)&Ch[o + 2] = __floats2half2_rn(v.z, v.w);
        }
    }
}

// ----------------------------------------------------------------------------
// Flash-style causal attention, fp32; emits fp16 for Wo GEMM.
// ----------------------------------------------------------------------------
#define APITCH 68

__global__ void __launch_bounds__(256) attn_kernel(const float* __restrict__ QKV,
                                                   __half* __restrict__ O)
{
    extern __shared__ float sm[];
    float* Qs = sm;
    float* Ks = sm + 64 * APITCH;
    float* Vs = sm + 2 * 64 * APITCH;
    float* Ps = sm + 3 * 64 * APITCH;

    int qb = blockIdx.x;
    int bh = blockIdx.y;
    int b = bh >> 4, h = bh & 15;
    int tid = threadIdx.x;
    int r = tid >> 2;
    int q = tid & 3;

    const size_t base = (size_t)b * Sn * 3072 + (size_t)h * 64;

    for (int i = tid; i < 64 * 16; i += 256) {
        int rr = i >> 4, c4 = (i & 15) << 2;
        float4 v = *(const float4*)(QKV + base + (size_t)(qb * 64 + rr) * 3072 + c4);
        float* dst = &Qs[rr * APITCH + c4];
        dst[0] = v.x * 0.125f; dst[1] = v.y * 0.125f;
        dst[2] = v.z * 0.125f; dst[3] = v.w * 0.125f;
    }

    float o[16];
    #pragma unroll
    for (int j = 0; j < 16; j++) o[j] = 0.0f;
    float m_prev = -1e30f, l_prev = 0.0f;
    const int qg = qb * 64 + r;

    for (int kb = 0; kb <= qb; kb++) {
        __syncthreads();
        for (int i = tid; i < 64 * 16; i += 256) {
            int rr = i >> 4, c4 = (i & 15) << 2;
            size_t off = base + (size_t)(kb * 64 + rr) * 3072 + c4;
            *(float4*)&Ks[rr * APITCH + c4] = *(const float4*)(QKV + off + 1024);
            *(float4*)&Vs[rr * APITCH + c4] = *(const float4*)(QKV + off + 2048);
        }
        __syncthreads();

        float s[16];
        #pragma unroll
        for (int j = 0; j < 16; j++) s[j] = 0.0f;
        #pragma unroll 4
        for (int k4 = 0; k4 < 16; k4++) {
            float4 qv = *(const float4*)&Qs[r * APITCH + (k4 << 2)];
            #pragma unroll
            for (int j = 0; j < 16; j++) {
                float4 kv = *(const float4*)&Ks[(q * 16 + j) * APITCH + (k4 << 2)];
                s[j] += qv.x * kv.x + qv.y * kv.y + qv.z * kv.z + qv.w * kv.w;
            }
        }

        float mloc = -1e30f;
        #pragma unroll
        for (int j = 0; j < 16; j++) {
            int tg = kb * 64 + q * 16 + j;
            if (tg > qg) s[j] = -1e30f;
            mloc = fmaxf(mloc, s[j]);
        }
        mloc = fmaxf(mloc, __shfl_xor_sync(0xffffffffu, mloc, 1));
        mloc = fmaxf(mloc, __shfl_xor_sync(0xffffffffu, mloc, 2));

        float m_new = fmaxf(m_prev, mloc);
        float alpha = __expf(m_prev - m_new);

        float lsum = 0.0f;
        #pragma unroll
        for (int j = 0; j < 16; j++) {
            float p = __expf(s[j] - m_new);
            Ps[r * APITCH + q * 16 + j] = p;
            lsum += p;
        }
        lsum += __shfl_xor_sync(0xffffffffu, lsum, 1);
        lsum += __shfl_xor_sync(0xffffffffu, lsum, 2);

        l_prev = l_prev * alpha + lsum;
        m_prev = m_new;
        #pragma unroll
        for (int j = 0; j < 16; j++) o[j] *= alpha;

        __syncwarp();

        #pragma unroll 4
        for (int t = 0; t < 64; t++) {
            float pv = Ps[r * APITCH + t];
            const float* vrow = &Vs[t * APITCH + q * 16];
            float4 v0 = *(const float4*)(vrow + 0);
            float4 v1 = *(const float4*)(vrow + 4);
            float4 v2 = *(const float4*)(vrow + 8);
            float4 v3 = *(const float4*)(vrow + 12);
            o[0]  += pv * v0.x; o[1]  += pv * v0.y; o[2]  += pv * v0.z; o[3]  += pv * v0.w;
            o[4]  += pv * v1.x; o[5]  += pv * v1.y; o[6]  += pv * v1.z; o[7]  += pv * v1.w;
            o[8]  += pv * v2.x; o[9]  += pv * v2.y; o[10] += pv * v2.z; o[11] += pv * v2.w;
            o[12] += pv * v3.x; o[13] += pv * v3.y; o[14] += pv * v3.z; o[15] += pv * v3.w;
        }
    }

    float linv = 1.0f / l_prev;
    size_t ob = (size_t)(b * Sn + qb * 64 + r) * Dn + h * 64 + q * 16;
    #pragma unroll
    for (int j = 0; j < 16; j += 2)
        *(__half2*)&O[ob + j] = __floats2half2_rn(o[j] * linv, o[j + 1] * linv);
}

// ----------------------------------------------------------------------------
// Launch (ordered so launch index 5 == QKV GEMM for ncu -s 5 -c 1).
// No nullptr arguments anywhere -- unused params get valid dummy pointers.
// ----------------------------------------------------------------------------
extern "C" void kernel_launch(void* const* d_in, const int* in_sizes, int n_in,
                              void* d_out, int out_size)
{
    const float* x     = (const float*)d_in[0];
    const float* Wq    = (const float*)d_in[1];
    const float* Wk    = (const float*)d_in[2];
    const float* Wv    = (const float*)d_in[3];
    const float* bq    = (const float*)d_in[4];
    const float* bk    = (const float*)d_in[5];
    const float* bv    = (const float*)d_in[6];
    const float* Wo    = (const float*)d_in[7];
    const float* bo    = (const float*)d_in[8];
    const float* W1    = (const float*)d_in[9];
    const float* b1    = (const float*)d_in[10];
    const float* W2    = (const float*)d_in[11];
    const float* b2    = (const float*)d_in[12];
    const float* gamma = (const float*)d_in[13];
    const float* beta  = (const float*)d_in[14];
    float* out = (float*)d_out;

    float *qkv, *bp;
    __half *hA, *at, *h1, *wq, *wo, *w1, *w2;
    cudaGetSymbolAddress((void**)&qkv, g_qkv);
    cudaGetSymbolAddress((void**)&bp,  g_bp);
    cudaGetSymbolAddress((void**)&hA,  g_hA);
    cudaGetSymbolAddress((void**)&at,  g_at);
    cudaGetSymbolAddress((void**)&h1,  g_h1);
    cudaGetSymbolAddress((void**)&wq,  g_wqkvT);
    cudaGetSymbolAddress((void**)&wo,  g_woT);
    cudaGetSymbolAddress((void**)&w1,  g_w1T);
    cudaGetSymbolAddress((void**)&w2,  g_w2T);

    cudaFuncSetAttribute(mma_gemm_kernel<false, false, true,  false>,
                         cudaFuncAttributeMaxDynamicSharedMemorySize, GEMM_SMEM);
    cudaFuncSetAttribute(mma_gemm_kernel<false, true,  true,  false>,
                         cudaFuncAttributeMaxDynamicSharedMemorySize, GEMM_SMEM);
    cudaFuncSetAttribute(mma_gemm_kernel<true,  false, false, true >,
                         cudaFuncAttributeMaxDynamicSharedMemorySize, GEMM_SMEM);

    dim3 tb(32, 8);
    // launches 0-4: QKV weight packs, bias pack, LN1
    transpose_pack_kernel<<<dim3(2, 32, 16), tb>>>(Wq, wq, Dn, HDn, (long long)Dn * HDn, 0,      Dn);
    transpose_pack_kernel<<<dim3(2, 32, 16), tb>>>(Wk, wq, Dn, HDn, (long long)Dn * HDn, Dn,     Dn);
    transpose_pack_kernel<<<dim3(2, 32, 16), tb>>>(Wv, wq, Dn, HDn, (long long)Dn * HDn, 2 * Dn, Dn);
    bias_pack_kernel<<<12, 256>>>(bq, bk, bv, bp);
    ln_kernel<<<Mrows, 256>>>(x, gamma, beta, hA);

    // launch 5: QKV GEMM  (ncu -s 5 -c 1 captures this)
    // residual unused (RES_=false): pass x as dummy. Ch unused (OUTB=false): pass hA.
    mma_gemm_kernel<false, false, true, false><<<dim3(3 * Dn / 128, Mrows / 128), 256, GEMM_SMEM>>>(
        hA, wq, bp, x, qkv, hA, 3 * Dn, Dn);

    // attention
    const int attn_smem = 4 * 64 * APITCH * (int)sizeof(float);
    cudaFuncSetAttribute(attn_kernel, cudaFuncAttributeMaxDynamicSharedMemorySize, attn_smem);
    attn_kernel<<<dim3(Sn / 64, Bn * Hn), 256, attn_smem>>>(qkv, at);

    // Wo pack + GEMM + residual (Ch unused: pass hA)
    transpose_pack_kernel<<<dim3(32, 32, 1),  tb>>>(Wo, wo, Dn, Dn, 0, 0, Dn);
    mma_gemm_kernel<false, true, true, false><<<dim3(Dn / 128, Mrows / 128), 256, GEMM_SMEM>>>(
        at, wo, bo, x, out, hA, Dn, Dn);

    // LN2
    ln_kernel<<<Mrows, 256>>>(out, gamma, beta, hA);

    // W1 pack + MLP1 + GELU (residual unused: pass x; Cf unused: pass qkv)
    transpose_pack_kernel<<<dim3(128, 32, 1), tb>>>(W1, w1, Dn, D4, 0, 0, Dn);
    mma_gemm_kernel<true, false, false, true><<<dim3(D4 / 128, Mrows / 128), 256, GEMM_SMEM>>>(
        hA, w1, b1, x, qkv, h1, D4, Dn);

    // W2 pack + MLP2 + residual (Ch unused: pass hA)
    transpose_pack_kernel<<<dim3(32, 128, 1), tb>>>(W2, w2, D4, Dn, 0, 0, D4);
    mma_gemm_kernel<false, true, true, false><<<dim3(Dn / 128, Mrows / 128), 256, GEMM_SMEM>>>(
        h1, w2, b2, out, out, hA, Dn, D4);
}

// round 9
// speedup vs baseline: 10.0391x; 8.3726x over previous
#include <cuda_runtime.h>
#include <cuda_fp16.h>
#include <cstdint>
#include <math.h>

// ----------------------------------------------------------------------------
// Problem constants
// ----------------------------------------------------------------------------
#define Bn   4
#define Sn   2048
#define Dn   1024
#define Hn   16
#define HDn  64
#define Mrows (Bn*Sn)          // 8192
#define D4   (4*Dn)            // 4096

// ----------------------------------------------------------------------------
// Scratch (device globals -- no allocations allowed)
// ----------------------------------------------------------------------------
__device__ __half g_qkv  [(size_t)Mrows * 3 * Dn];   // fp16 now (attention uses mma)
__device__ __half g_hA   [(size_t)Mrows * Dn];
__device__ __half g_at   [(size_t)Mrows * Dn];
__device__ __half g_h1   [(size_t)Mrows * D4];
__device__ __half g_wqkvT[(size_t)3 * Dn * Dn];
__device__ __half g_woT  [(size_t)Dn * Dn];
__device__ __half g_w1T  [(size_t)D4 * Dn];
__device__ __half g_w2T  [(size_t)Dn * D4];
__device__ float  g_bp[3 * Dn];

__device__ __forceinline__ uint32_t smem_u32(const void* p) {
    uint32_t a;
    asm("{ .reg .u64 t; cvta.to.shared.u64 t, %1; cvt.u32.u64 %0, t; }" : "=r"(a) : "l"(p));
    return a;
}
__device__ __forceinline__ void cp_async16(void* dst, const void* src) {
    asm volatile("cp.async.cg.shared.global [%0], [%1], 16;"
                 :: "r"(smem_u32(dst)), "l"(src) : "memory");
}
#define CP_COMMIT() asm volatile("cp.async.commit_group;" ::: "memory")
#define CP_WAIT(n)  asm volatile("cp.async.wait_group %0;" :: "n"(n) : "memory")

__device__ __forceinline__ void ldsm_x4(uint32_t* r, uint32_t a) {
    asm volatile("ldmatrix.sync.aligned.m8n8.x4.shared.b16 {%0,%1,%2,%3}, [%4];"
                 : "=r"(r[0]), "=r"(r[1]), "=r"(r[2]), "=r"(r[3]) : "r"(a));
}
__device__ __forceinline__ void ldsm_x4_t(uint32_t* r, uint32_t a) {
    asm volatile("ldmatrix.sync.aligned.m8n8.x4.trans.shared.b16 {%0,%1,%2,%3}, [%4];"
                 : "=r"(r[0]), "=r"(r[1]), "=r"(r[2]), "=r"(r[3]) : "r"(a));
}
__device__ __forceinline__ void mma16816(float* d, const uint32_t* a, const uint32_t* b) {
    asm volatile("mma.sync.aligned.m16n8k16.row.col.f32.f16.f16.f32 "
                 "{%0,%1,%2,%3}, {%4,%5,%6,%7}, {%8,%9}, {%0,%1,%2,%3};"
                 : "+f"(d[0]), "+f"(d[1]), "+f"(d[2]), "+f"(d[3])
                 : "r"(a[0]), "r"(a[1]), "r"(a[2]), "r"(a[3]), "r"(b[0]), "r"(b[1]));
}

// ----------------------------------------------------------------------------
// Fused QKV transpose+pack (one launch): z/16 selects Wq/Wk/Wv, z%16 = head.
// src [D,HD] per head -> wqkvT rows [w*1024 + head*64 + n][k].
// ----------------------------------------------------------------------------
__global__ void qkv_pack_kernel(const float* __restrict__ Wq,
                                const float* __restrict__ Wk,
                                const float* __restrict__ Wv,
                                __half* __restrict__ dst)
{
    __shared__ float t[32][33];
    int z = blockIdx.z;
    int w = z >> 4, zh = z & 15;
    const float* src = (w == 0 ? Wq : w == 1 ? Wk : Wv) + (size_t)zh * Dn * HDn;
    int n0 = blockIdx.x * 32, k0 = blockIdx.y * 32;
    int tx = threadIdx.x, ty = threadIdx.y;
    #pragma unroll
    for (int j = 0; j < 4; j++) {
        int k = k0 + ty + j * 8;
        t[ty + j * 8][tx] = src[(size_t)k * HDn + n0 + tx];
    }
    __syncthreads();
    int row_base = w * Dn + zh * HDn;
    #pragma unroll
    for (int j = 0; j < 4; j++) {
        int n = n0 + ty + j * 8;
        size_t o = (size_t)(row_base + n) * Dn + k0 + tx;
        dst[o] = __float2half_rn(t[tx][ty + j * 8]);
    }
}

// General transpose+pack for Wo/W1/W2
__global__ void transpose_pack_kernel(const float* __restrict__ src,
                                      __half* __restrict__ dst,
                                      int Ks, int Ns)
{
    __shared__ float t[32][33];
    int n0 = blockIdx.x * 32, k0 = blockIdx.y * 32;
    int tx = threadIdx.x, ty = threadIdx.y;
    #pragma unroll
    for (int j = 0; j < 4; j++) {
        int k = k0 + ty + j * 8;
        t[ty + j * 8][tx] = src[(size_t)k * Ns + n0 + tx];
    }
    __syncthreads();
    #pragma unroll
    for (int j = 0; j < 4; j++) {
        int n = n0 + ty + j * 8;
        size_t o = (size_t)n * Ks + k0 + tx;
        dst[o] = __float2half_rn(t[tx][ty + j * 8]);
    }
}

__global__ void bias_pack_kernel(const float* __restrict__ bq,
                                 const float* __restrict__ bk,
                                 const float* __restrict__ bv,
                                 float* __restrict__ bp)
{
    int idx = blockIdx.x * 256 + threadIdx.x;
    if (idx < 3 * Dn) {
        int w = idx >> 10, c = idx & 1023;
        bp[idx] = (w == 0 ? bq : w == 1 ? bk : bv)[c];
    }
}

// ----------------------------------------------------------------------------
// LayerNorm -> fp16.
// ----------------------------------------------------------------------------
__global__ void __launch_bounds__(256) ln_kernel(const float* __restrict__ X,
                                                 const float* __restrict__ gamma,
                                                 const float* __restrict__ beta,
                                                 __half* __restrict__ Y)
{
    int row = blockIdx.x;
    int tid = threadIdx.x;
    float4 xv = ((const float4*)(X + (size_t)row * Dn))[tid];

    __shared__ float red[8];
    float s = xv.x + xv.y + xv.z + xv.w;
    #pragma unroll
    for (int o = 16; o > 0; o >>= 1) s += __shfl_xor_sync(0xffffffffu, s, o);
    if ((tid & 31) == 0) red[tid >> 5] = s;
    __syncthreads();
    float mu = (red[0]+red[1]+red[2]+red[3]+red[4]+red[5]+red[6]+red[7]) * (1.0f / Dn);
    __syncthreads();

    float dx = xv.x - mu, dy = xv.y - mu, dz = xv.z - mu, dw = xv.w - mu;
    float sq = dx*dx + dy*dy + dz*dz + dw*dw;
    #pragma unroll
    for (int o = 16; o > 0; o >>= 1) sq += __shfl_xor_sync(0xffffffffu, sq, o);
    if ((tid & 31) == 0) red[tid >> 5] = sq;
    __syncthreads();
    float var = (red[0]+red[1]+red[2]+red[3]+red[4]+red[5]+red[6]+red[7]) * (1.0f / Dn);
    float inv = rsqrtf(var + 1e-5f);

    float4 gv = ((const float4*)gamma)[tid];
    float4 bv = ((const float4*)beta)[tid];
    float o0 = dx*inv*gv.x + bv.x, o1 = dy*inv*gv.y + bv.y;
    float o2 = dz*inv*gv.z + bv.z, o3 = dw*inv*gv.w + bv.w;

    size_t off = (size_t)row * Dn + tid * 4;
    *(__half2*)&Y[off]     = __floats2half2_rn(o0, o1);
    *(__half2*)&Y[off + 2] = __floats2half2_rn(o2, o3);
}

// ----------------------------------------------------------------------------
// Raw mma.sync fp16 GEMM (validated in R8), 3-stage cp.async, BK=64, 8 warps.
// ----------------------------------------------------------------------------
__device__ __forceinline__ float gelu_exact(float v) {
    return 0.5f * v * (1.0f + erff(v * 0.70710678118654752f));
}

#define BK     64
#define KPITCH 72
#define TILEB  (128 * KPITCH * 2)
#define STAGEB (2 * TILEB)
#define NSTAGE 3
#define GEMM_SMEM (NSTAGE * STAGEB)
#define SPITCH 132

template <bool GELU_, bool RES_, bool OUTF, bool OUTB>
__global__ void __launch_bounds__(256) mma_gemm_kernel(
    const __half* __restrict__ A, const __half* __restrict__ B,
    const float* __restrict__ bias, const float* __restrict__ residual,
    float* __restrict__ Cf, __half* __restrict__ Ch,
    int N, int K)
{
    extern __shared__ __align__(128) char smem[];
    float* stg = (float*)smem;

    const int tid = threadIdx.x;
    const int wid = tid >> 5;
    const int lane = tid & 31;
    const int wm = wid >> 2;
    const int wn = wid & 3;
    const int bx = blockIdx.x, by = blockIdx.y;

    const size_t arow = (size_t)by * 128;
    const size_t brow = (size_t)bx * 128;

    auto load_chunk = [&](int kc, int st) {
        char* base = smem + st * STAGEB;
        __half* A_s = (__half*)(base);
        __half* B_s = (__half*)(base + TILEB);
        #pragma unroll
        for (int i = 0; i < 4; i++) {
            int idx = tid + i * 256;
            int row = idx >> 3, c = idx & 7;
            size_t ao = (arow + row) * (size_t)K + kc * BK + c * 8;
            size_t bo = (brow + row) * (size_t)K + kc * BK + c * 8;
            int so = row * KPITCH + c * 8;
            cp_async16(&A_s[so], A + ao);
            cp_async16(&B_s[so], B + bo);
        }
    };

    float acc[4][4][4];
    #pragma unroll
    for (int i = 0; i < 4; i++)
        #pragma unroll
        for (int n = 0; n < 4; n++)
            #pragma unroll
            for (int e = 0; e < 4; e++) acc[i][n][e] = 0.0f;

    const int a_r  = wm * 64 + (lane & 15);
    const int a_k  = (lane >> 4) << 3;
    const int b_r  = wn * 32 + ((lane >> 4) << 3) + (lane & 7);
    const int b_k  = ((lane >> 3) & 1) << 3;

    const int nk = K / BK;
    load_chunk(0, 0); CP_COMMIT();
    load_chunk(1, 1); CP_COMMIT();

    for (int kc = 0; kc < nk; kc++) {
        const int st = kc % NSTAGE;
        if (kc + 2 < nk) { load_chunk(kc + 2, (kc + 2) % NSTAGE); CP_COMMIT(); }
        if      (kc + 2 < nk) CP_WAIT(2);
        else if (kc + 1 < nk) CP_WAIT(1);
        else                  CP_WAIT(0);
        __syncthreads();

        char* base = smem + st * STAGEB;
        const uint32_t uA = smem_u32(base);
        const uint32_t uB = smem_u32(base + TILEB);

        #pragma unroll
        for (int ks = 0; ks < BK / 16; ks++) {
            uint32_t a[4][4], b[2][4];
            const int kof = ks * 16;
            #pragma unroll
            for (int i = 0; i < 4; i++)
                ldsm_x4(a[i], uA + (uint32_t)(((a_r + i * 16) * KPITCH + kof + a_k) * 2));
            #pragma unroll
            for (int g = 0; g < 2; g++)
                ldsm_x4(b[g], uB + (uint32_t)(((b_r + g * 16) * KPITCH + kof + b_k) * 2));
            #pragma unroll
            for (int i = 0; i < 4; i++)
                #pragma unroll
                for (int n = 0; n < 4; n++)
                    mma16816(acc[i][n], a[i], &b[n >> 1][(n & 1) * 2]);
        }
        __syncthreads();
    }

    const int c_r = lane >> 2;
    const int c_c = (lane & 3) << 1;
    #pragma unroll
    for (int i = 0; i < 4; i++)
        #pragma unroll
        for (int n = 0; n < 4; n++) {
            int r0 = wm * 64 + i * 16 + c_r;
            int c0 = wn * 32 + n * 8 + c_c;
            stg[r0 * SPITCH + c0]           = acc[i][n][0];
            stg[r0 * SPITCH + c0 + 1]       = acc[i][n][1];
            stg[(r0 + 8) * SPITCH + c0]     = acc[i][n][2];
            stg[(r0 + 8) * SPITCH + c0 + 1] = acc[i][n][3];
        }
    __syncthreads();

    const int cc = tid & 31;
    const int ncol = bx * 128 + cc * 4;
    float4 bb = *(const float4*)&bias[ncol];
    #pragma unroll 4
    for (int rr = 0; rr < 16; rr++) {
        int row = (tid >> 5) * 16 + rr;
        size_t m = arow + row;
        float4 v = *(float4*)&stg[row * SPITCH + cc * 4];
        v.x += bb.x; v.y += bb.y; v.z += bb.z; v.w += bb.w;
        if (GELU_) {
            v.x = gelu_exact(v.x); v.y = gelu_exact(v.y);
            v.z = gelu_exact(v.z); v.w = gelu_exact(v.w);
        }
        if (RES_) {
            float4 rv = *(const float4*)&residual[m * N + ncol];
            v.x += rv.x; v.y += rv.y; v.z += rv.z; v.w += rv.w;
        }
        if (OUTF) *(float4*)&Cf[m * N + ncol] = v;
        if (OUTB) {
            size_t o = m * N + ncol;
            *(__half2*)&Ch[o]     = __floats2half2_rn(v.x, v.y);
            *(__half2*)&Ch[o + 2] = __floats2half2_rn(v.z, v.w);
        }
    }
}

// ----------------------------------------------------------------------------
// Tensor-core flash attention. 128 threads (4 warps), 64-query tile, one (b,h).
// QKV fp16: Q @ h*64, K @ 1024+h*64, V @ 2048+h*64 within each 3072-row.
// S = Q.K^T via mma (fp32 acc), fp32 online softmax in regs, P fp16 in-reg,
// O += P.V via mma with ldmatrix.trans on V. Double-buffered cp.async K/V.
// ----------------------------------------------------------------------------
#define AQP 72                           // half pitch (64 + 8)
#define ATT_SMEM (5 * 64 * AQP * 2)      // Q + K[2] + V[2] = 46080 B

__global__ void __launch_bounds__(128) attn_mma_kernel(const __half* __restrict__ QKV,
                                                       __half* __restrict__ O)
{
    extern __shared__ __align__(16) __half smh[];
    __half* Qs = smh;                                   // [64][AQP]

    int qb = blockIdx.x;
    int bh = blockIdx.y;
    int b = bh >> 4, h = bh & 15;
    int tid = threadIdx.x, w = tid >> 5, lane = tid & 31;

    const size_t rowbase = (size_t)(b * Sn) * 3072 + (size_t)h * 64;

    // Q tile load (cp.async)
    #pragma unroll
    for (int i = 0; i < 4; i++) {
        int idx = tid + i * 128;
        int row = idx >> 3, c = idx & 7;
        cp_async16(&Qs[row * AQP + c * 8],
                   QKV + rowbase + (size_t)(qb * 64 + row) * 3072 + c * 8);
    }
    CP_COMMIT();

    auto load_kv = [&](int kb, int st) {
        __half* K_s = smh + 64 * AQP * (1 + st);
        __half* V_s = smh + 64 * AQP * (3 + st);
        #pragma unroll
        for (int i = 0; i < 4; i++) {
            int idx = tid + i * 128;
            int row = idx >> 3, c = idx & 7;
            size_t src = rowbase + (size_t)(kb * 64 + row) * 3072 + c * 8;
            cp_async16(&K_s[row * AQP + c * 8], QKV + src + 1024);
            cp_async16(&V_s[row * AQP + c * 8], QKV + src + 2048);
        }
    };
    load_kv(0, 0); CP_COMMIT();
    CP_WAIT(0);
    __syncthreads();

    // Q fragments (hoisted; constant over kb)
    uint32_t aQ[4][4];
    {
        const uint32_t uQ = smem_u32(Qs);
        int a_r = w * 16 + (lane & 15);
        int a_k = (lane >> 4) << 3;
        #pragma unroll
        for (int t = 0; t < 4; t++)
            ldsm_x4(aQ[t], uQ + (uint32_t)((a_r * AQP + t * 16 + a_k) * 2));
    }

    // fragment address components
    const int bk_r = ((lane >> 4) << 3) + (lane & 7);   // K rows within n16 group
    const int bk_k = ((lane >> 3) & 1) << 3;
    const int bv_r = (((lane >> 3) & 1) << 3) + (lane & 7);  // V k-row within k16
    const int bv_c = (lane >> 4) << 3;                        // V col within n16

    float o[8][4];
    #pragma unroll
    for (int j = 0; j < 8; j++)
        #pragma unroll
        for (int e = 0; e < 4; e++) o[j][e] = 0.0f;
    float m0 = -1e30f, m1 = -1e30f, l0 = 0.0f, l1 = 0.0f;

    const int qg0 = qb * 64 + w * 16 + (lane >> 2);   // global row for regs 0,1 (row1 = +8)

    for (int kb = 0; kb <= qb; kb++) {
        const int st = kb & 1;
        if (kb < qb) { load_kv(kb + 1, st ^ 1); CP_COMMIT(); }

        const uint32_t uK = smem_u32(smh + 64 * AQP * (1 + st));
        const uint32_t uV = smem_u32(smh + 64 * AQP * (3 + st));

        // ---- S = Q.K^T ----
        float s[8][4];
        #pragma unroll
        for (int j = 0; j < 8; j++)
            #pragma unroll
            for (int e = 0; e < 4; e++) s[j][e] = 0.0f;
        #pragma unroll
        for (int t = 0; t < 4; t++) {
            uint32_t bK[4][4];
            #pragma unroll
            for (int g = 0; g < 4; g++)
                ldsm_x4(bK[g], uK + (uint32_t)(((g * 16 + bk_r) * AQP + t * 16 + bk_k) * 2));
            #pragma unroll
            for (int j = 0; j < 8; j++)
                mma16816(s[j], aQ[t], &bK[j >> 1][(j & 1) * 2]);
        }

        // scale + causal mask (diagonal tile only)
        #pragma unroll
        for (int j = 0; j < 8; j++)
            #pragma unroll
            for (int e = 0; e < 4; e++) s[j][e] *= 0.125f;
        if (kb == qb) {
            #pragma unroll
            for (int j = 0; j < 8; j++) {
                int col = kb * 64 + j * 8 + (lane & 3) * 2;
                if (col     > qg0)     s[j][0] = -1e30f;
                if (col + 1 > qg0)     s[j][1] = -1e30f;
                if (col     > qg0 + 8) s[j][2] = -1e30f;
                if (col + 1 > qg0 + 8) s[j][3] = -1e30f;
            }
        }

        // ---- online softmax (fp32) ----
        float ml0 = -1e30f, ml1 = -1e30f;
        #pragma unroll
        for (int j = 0; j < 8; j++) {
            ml0 = fmaxf(ml0, fmaxf(s[j][0], s[j][1]));
            ml1 = fmaxf(ml1, fmaxf(s[j][2], s[j][3]));
        }
        ml0 = fmaxf(ml0, __shfl_xor_sync(0xffffffffu, ml0, 1));
        ml0 = fmaxf(ml0, __shfl_xor_sync(0xffffffffu, ml0, 2));
        ml1 = fmaxf(ml1, __shfl_xor_sync(0xffffffffu, ml1, 1));
        ml1 = fmaxf(ml1, __shfl_xor_sync(0xffffffffu, ml1, 2));

        float mn0 = fmaxf(m0, ml0), mn1 = fmaxf(m1, ml1);
        float al0 = __expf(m0 - mn0), al1 = __expf(m1 - mn1);

        float ls0 = 0.0f, ls1 = 0.0f;
        uint32_t pfrag[4][4];
        #pragma unroll
        for (int j = 0; j < 8; j++) {
            float p0 = __expf(s[j][0] - mn0);
            float p1 = __expf(s[j][1] - mn0);
            float p2 = __expf(s[j][2] - mn1);
            float p3 = __expf(s[j][3] - mn1);
            ls0 += p0 + p1; ls1 += p2 + p3;
            int t = j >> 1, hi = (j & 1) * 2;
            __half2 h01 = __floats2half2_rn(p0, p1);
            __half2 h23 = __floats2half2_rn(p2, p3);
            pfrag[t][hi]     = *(uint32_t*)&h01;
            pfrag[t][hi + 1] = *(uint32_t*)&h23;
        }
        ls0 += __shfl_xor_sync(0xffffffffu, ls0, 1);
        ls0 += __shfl_xor_sync(0xffffffffu, ls0, 2);
        ls1 += __shfl_xor_sync(0xffffffffu, ls1, 1);
        ls1 += __shfl_xor_sync(0xffffffffu, ls1, 2);

        l0 = l0 * al0 + ls0;  l1 = l1 * al1 + ls1;
        m0 = mn0;             m1 = mn1;
        #pragma unroll
        for (int j = 0; j < 8; j++) {
            o[j][0] *= al0; o[j][1] *= al0;
            o[j][2] *= al1; o[j][3] *= al1;
        }

        // ---- O += P.V ----
        #pragma unroll
        for (int t = 0; t < 4; t++) {
            uint32_t bV[4][4];
            #pragma unroll
            for (int g = 0; g < 4; g++)
                ldsm_x4_t(bV[g], uV + (uint32_t)(((t * 16 + bv_r) * AQP + g * 16 + bv_c) * 2));
            #pragma unroll
            for (int j = 0; j < 8; j++)
                mma16816(o[j], pfrag[t], &bV[j >> 1][(j & 1) * 2]);
        }

        if (kb < qb) CP_WAIT(0);
        __syncthreads();
    }

    float inv0 = 1.0f / l0, inv1 = 1.0f / l1;
    size_t ob = (size_t)(b * Sn + qb * 64 + w * 16 + (lane >> 2)) * Dn + h * 64;
    #pragma unroll
    for (int j = 0; j < 8; j++) {
        int col = j * 8 + (lane & 3) * 2;
        __half2 v0 = __floats2half2_rn(o[j][0] * inv0, o[j][1] * inv0);
        __half2 v1 = __floats2half2_rn(o[j][2] * inv1, o[j][3] * inv1);
        *(__half2*)&O[ob + col]           = v0;
        *(__half2*)&O[ob + 8 * Dn + col]  = v1;
    }
}

// ----------------------------------------------------------------------------
// Launch (qkv_pack(0), bias(1), ln1(2), QKV GEMM(3) <- profiled, attn(4), ...)
// ----------------------------------------------------------------------------
extern "C" void kernel_launch(void* const* d_in, const int* in_sizes, int n_in,
                              void* d_out, int out_size)
{
    const float* x     = (const float*)d_in[0];
    const float* Wq    = (const float*)d_in[1];
    const float* Wk    = (const float*)d_in[2];
    const float* Wv    = (const float*)d_in[3];
    const float* bq    = (const float*)d_in[4];
    const float* bk    = (const float*)d_in[5];
    const float* bv    = (const float*)d_in[6];
    const float* Wo    = (const float*)d_in[7];
    const float* bo    = (const float*)d_in[8];
    const float* W1    = (const float*)d_in[9];
    const float* b1    = (const float*)d_in[10];
    const float* W2    = (const float*)d_in[11];
    const float* b2    = (const float*)d_in[12];
    const float* gamma = (const float*)d_in[13];
    const float* beta  = (const float*)d_in[14];
    float* out = (float*)d_out;

    float *bp;
    __half *qkv, *hA, *at, *h1, *wq, *wo, *w1, *w2;
    cudaGetSymbolAddress((void**)&qkv, g_qkv);
    cudaGetSymbolAddress((void**)&bp,  g_bp);
    cudaGetSymbolAddress((void**)&hA,  g_hA);
    cudaGetSymbolAddress((void**)&at,  g_at);
    cudaGetSymbolAddress((void**)&h1,  g_h1);
    cudaGetSymbolAddress((void**)&wq,  g_wqkvT);
    cudaGetSymbolAddress((void**)&wo,  g_woT);
    cudaGetSymbolAddress((void**)&w1,  g_w1T);
    cudaGetSymbolAddress((void**)&w2,  g_w2T);

    cudaFuncSetAttribute(mma_gemm_kernel<false, false, false, true >,
                         cudaFuncAttributeMaxDynamicSharedMemorySize, GEMM_SMEM);
    cudaFuncSetAttribute(mma_gemm_kernel<false, true,  true,  false>,
                         cudaFuncAttributeMaxDynamicSharedMemorySize, GEMM_SMEM);
    cudaFuncSetAttribute(mma_gemm_kernel<true,  false, false, true >,
                         cudaFuncAttributeMaxDynamicSharedMemorySize, GEMM_SMEM);
    cudaFuncSetAttribute(attn_mma_kernel,
                         cudaFuncAttributeMaxDynamicSharedMemorySize, ATT_SMEM);

    dim3 tb(32, 8);
    // 0: fused QKV weight pack
    qkv_pack_kernel<<<dim3(2, 32, 48), tb>>>(Wq, Wk, Wv, wq);
    // 1: bias pack
    bias_pack_kernel<<<12, 256>>>(bq, bk, bv, bp);
    // 2: LN1
    ln_kernel<<<Mrows, 256>>>(x, gamma, beta, hA);

    // 3: QKV GEMM -> fp16 qkv   (ncu capture lands here)
    mma_gemm_kernel<false, false, false, true><<<dim3(3 * Dn / 128, Mrows / 128), 256, GEMM_SMEM>>>(
        hA, wq, bp, x, out, qkv, 3 * Dn, Dn);

    // 4: tensor-core attention -> fp16 at
    attn_mma_kernel<<<dim3(Sn / 64, Bn * Hn), 128, ATT_SMEM>>>(qkv, at);

    // 5-6: Wo pack + GEMM (+x residual) -> fp32 out
    transpose_pack_kernel<<<dim3(32, 32), tb>>>(Wo, wo, Dn, Dn);
    mma_gemm_kernel<false, true, true, false><<<dim3(Dn / 128, Mrows / 128), 256, GEMM_SMEM>>>(
        at, wo, bo, x, out, qkv, Dn, Dn);

    // 7: LN2
    ln_kernel<<<Mrows, 256>>>(out, gamma, beta, hA);

    // 8-9: W1 pack + MLP1 (+GELU) -> fp16 h1
    transpose_pack_kernel<<<dim3(128, 32), tb>>>(W1, w1, Dn, D4);
    mma_gemm_kernel<true, false, false, true><<<dim3(D4 / 128, Mrows / 128), 256, GEMM_SMEM>>>(
        hA, w1, b1, x, out, h1, D4, Dn);

    // 10-11: W2 pack + MLP2 (+out residual) -> fp32 out
    transpose_pack_kernel<<<dim3(32, 128), tb>>>(W2, w2, D4, Dn);
    mma_gemm_kernel<false, true, true, false><<<dim3(Dn / 128, Mrows / 128), 256, GEMM_SMEM>>>(
        h1, w2, b2, out, out, qkv, Dn, D4);
}